// round 13
// baseline (speedup 1.0000x reference)
#include <cuda_runtime.h>
#include <cuda_fp16.h>
#include <math.h>
#include <stdint.h>

#define N_ 50000
#define F_ 128
#define G_ 3
#define E_ 600000
#define NF ((size_t)N_ * F_)
#define SB_ 49
#define GEMM_BX 391
#define GEMM_BLOCKS (G_ * GEMM_BX)
#define CSRB 256
#define GV_BLOCKS (98 * G_)
#define U_BLOCKS G_
#define SUM3_BLOCKS ((int)((NF / 2 + 255) / 256))
#define FUSE_BLOCKS ((N_ + 7) / 8)

#define XS_STRIDE 36
#define WS_STRIDE 136
#define XS_WORDS (128 * XS_STRIDE)
#define WS_WORDS (32 * WS_STRIDE)
#define GEMM_SMEM_WORDS (2 * (XS_WORDS + WS_WORDS))
#define GEMM_SMEM_BYTES (GEMM_SMEM_WORDS * 4)   // 71680

// ------------------------- static device scratch -------------------------
__device__ __align__(16) float d_pre  [G_ * N_ * F_];
__device__ __align__(16) float d_conv1[G_ * N_ * F_];
__device__ __align__(16) float d_enc  [G_ * N_ * F_];
__device__ __align__(16) float d_efin [G_ * N_ * F_];
__device__ __align__(16) __half d_htmp [G_ * N_ * F_];
__device__ __align__(16) __half d_ow1h [2 * G_ * N_ * F_];  // fp16 [own1|oth1]
__device__ __align__(16) __half d_h6   [2 * G_ * N_ * F_];  // fp16 level-2 sources
__device__ __align__(16) __half d_own2h[G_ * N_ * F_];
__device__ __align__(16) __half d_oth2h[G_ * N_ * F_];
__device__ __align__(16) __half d_hS1  [N_ * F_];

__device__ int   d_deg   [G_ * N_];
__device__ int   d_rowptr[G_ * (N_ + 1)];
__device__ int   d_cur   [G_ * N_];
__device__ int   d_col   [G_ * E_];
__device__ int   d_bsum  [G_ * SB_];
__device__ __align__(16) float d_dinv  [G_ * N_];
__device__ float d_gv    [G_ * F_];
__device__ __align__(16) float d_u     [G_ * F_];
__device__ float d_parts [16];
__device__ int   d_e64;
__device__ int   d_done;

// ------------------------- edge load helper -------------------------------
__device__ __forceinline__ int load_edge(const void* edges, size_t idx, int e64) {
    if (e64) return (int)((const long long*)edges)[idx];
    return ((const int*)edges)[idx];
}

// ------------------------- L1: detect dtype + zero -------------------------
__global__ void detect_zero_k(const void* __restrict__ edges) {
    if (blockIdx.x == 0) {
        const unsigned int* w = (const unsigned int*)edges;
        __shared__ int any;
        if (threadIdx.x == 0) any = 0;
        __syncthreads();
        for (int i = threadIdx.x; i < 2048; i += blockDim.x)
            if (w[2 * i + 1] != 0u) any = 1;
        __syncthreads();
        if (threadIdx.x == 0) { d_e64 = any ? 0 : 1; d_done = 0; }
    } else {
        int i = (blockIdx.x - 1) * blockDim.x + threadIdx.x;
        if (i < G_ * N_) d_deg[i] = 0;
        if (i < G_ * F_) d_gv[i] = 0.f;
        if (i < 16) d_parts[i] = 0.f;
    }
}

// ------------------------- grid-strided CSR bodies -------------------------
__device__ __forceinline__ void count_deg_body(const void* edges, int bx) {
    int e64 = d_e64;
    for (int i = bx * 256 + threadIdx.x; i < G_ * E_; i += CSRB * 256) {
        int g = i / E_, e = i - g * E_;
        int dst = load_edge(edges, (size_t)g * 2 * E_ + E_ + e, e64);
        atomicAdd(&d_deg[g * N_ + dst], 1);
    }
}

__device__ __forceinline__ void fill_csr_body(const void* edges, int bx) {
    int e64 = d_e64;
    for (int i = bx * 256 + threadIdx.x; i < G_ * E_; i += CSRB * 256) {
        int g = i / E_, e = i - g * E_;
        int src = load_edge(edges, (size_t)g * 2 * E_ + e, e64);
        int dst = load_edge(edges, (size_t)g * 2 * E_ + E_ + e, e64);
        int pos = atomicAdd(&d_cur[g * N_ + dst], 1);
        d_col[(size_t)g * E_ + pos] = src;
    }
}

// --- 2-phase multi-block prefix scan (+ dinv + cur fused) ---
__global__ void scan_p1_k() {
    int g = blockIdx.y, b = blockIdx.x;
    int tid = threadIdx.x;
    int base = b * 1024 + tid * 4;
    int v = 0;
#pragma unroll
    for (int j = 0; j < 4; j++) {
        int idx = base + j;
        if (idx < N_) v += d_deg[g * N_ + idx];
    }
    __shared__ int red[256];
    red[tid] = v;
    __syncthreads();
    for (int s = 128; s > 0; s >>= 1) {
        if (tid < s) red[tid] += red[tid + s];
        __syncthreads();
    }
    if (tid == 0) d_bsum[g * SB_ + b] = red[0];
}

__global__ void scan_p3_k() {
    int g = blockIdx.y, b = blockIdx.x;
    int tid = threadIdx.x;
    __shared__ int soff;
    if (tid == 0) {
        int acc = 0;
        for (int i = 0; i < b; i++) acc += d_bsum[g * SB_ + i];
        soff = acc;
    }
    int base = b * 1024 + tid * 4;
    int v[4]; int s = 0;
#pragma unroll
    for (int j = 0; j < 4; j++) {
        int idx = base + j;
        v[j] = (idx < N_) ? d_deg[g * N_ + idx] : 0;
        s += v[j];
    }
    __shared__ int sc[256];
    sc[tid] = s;
    __syncthreads();
    for (int st = 1; st < 256; st <<= 1) {
        int t = (tid >= st) ? sc[tid - st] : 0;
        __syncthreads();
        sc[tid] += t;
        __syncthreads();
    }
    int run = soff + sc[tid] - s;
    if (b == 0 && tid == 0) d_rowptr[g * (N_ + 1)] = 0;
#pragma unroll
    for (int j = 0; j < 4; j++) {
        int idx = base + j;
        if (idx < N_) {
            d_cur[g * N_ + idx] = run;
            run += v[j];
            d_rowptr[g * (N_ + 1) + idx + 1] = run;
            d_dinv[g * N_ + idx] = rsqrtf((float)(v[j] + 1));
        }
    }
}

// ------------------------- tf32 GEMM body (double-buffered) ----------------
__device__ __forceinline__ uint32_t f2tf32(float x) {
    uint32_t r; asm("cvt.rna.tf32.f32 %0, %1;" : "=r"(r) : "f"(x)); return r;
}

__device__ __forceinline__ void mma_tf32(float* c, const uint32_t* a,
                                         uint32_t b0, uint32_t b1) {
    asm volatile(
        "mma.sync.aligned.m16n8k8.row.col.f32.tf32.tf32.f32 "
        "{%0,%1,%2,%3}, {%4,%5,%6,%7}, {%8,%9}, {%0,%1,%2,%3};"
        : "+f"(c[0]), "+f"(c[1]), "+f"(c[2]), "+f"(c[3])
        : "r"(a[0]), "r"(a[1]), "r"(a[2]), "r"(a[3]), "r"(b0), "r"(b1));
}

__device__ __forceinline__ void gemm_body(
    int g, int rb,
    const void* __restrict__ Xbase, const float* __restrict__ Wbase,
    const float* __restrict__ bbase, void* __restrict__ Ybase,
    const void* __restrict__ X2base, const float* __restrict__ W2base,
    int wstride, int bstride, int half_out, int half_in)
{
    const void* X  = half_in ? (const void*)((const __half*)Xbase + (size_t)g * NF)
                             : (const void*)((const float*)Xbase + (size_t)g * NF);
    const void* X2 = X2base ? (half_in ? (const void*)((const __half*)X2base + (size_t)g * NF)
                                       : (const void*)((const float*)X2base + (size_t)g * NF))
                            : nullptr;
    const float* W  = Wbase + (size_t)g * wstride;
    const float* bias = bbase ? (bbase + (size_t)g * bstride) : nullptr;
    int row0 = rb * 128;

    extern __shared__ __align__(16) uint32_t sdyn[];
    uint32_t* Xs0 = sdyn;
    uint32_t* Xs1 = sdyn + XS_WORDS;
    uint32_t* Ws0 = sdyn + 2 * XS_WORDS;
    uint32_t* Ws1 = sdyn + 2 * XS_WORDS + WS_WORDS;

    int tid = threadIdx.x;
    int lane = tid & 31;
    int wid = tid >> 5;
    int wm = (wid >> 1) * 32;
    int wn = (wid & 1) * 64;

    float acc[2][8][4];
#pragma unroll
    for (int mt = 0; mt < 2; mt++)
#pragma unroll
        for (int nt = 0; nt < 8; nt++)
#pragma unroll
            for (int q = 0; q < 4; q++) acc[mt][nt][q] = 0.f;

    int nchunks = X2 ? 8 : 4;

    float4 pxv[4], pwv[4];
#define LOAD_CHUNK(ch)                                                        \
    {                                                                         \
        int k0 = ((ch) & 3) * 32;                                             \
        _Pragma("unroll")                                                     \
        for (int t = 0; t < 4; t++) {                                         \
            int idx = tid + t * 256;                                          \
            int r = idx >> 3, c = (idx & 7) * 4;                              \
            int row = row0 + r;                                               \
            pxv[t] = make_float4(0.f, 0.f, 0.f, 0.f);                         \
            if (row < N_) {                                                   \
                if (half_in) {                                                \
                    const __half* Xh = ((ch) < 4) ? (const __half*)X : (const __half*)X2; \
                    uint2 hv = *(const uint2*)(Xh + (size_t)row * 128 + k0 + c); \
                    float2 lo = __half22float2(*(__half2*)&hv.x);             \
                    float2 hi = __half22float2(*(__half2*)&hv.y);             \
                    pxv[t] = make_float4(lo.x, lo.y, hi.x, hi.y);             \
                } else {                                                      \
                    const float* Xf = ((ch) < 4) ? (const float*)X : (const float*)X2; \
                    pxv[t] = *(const float4*)(Xf + (size_t)row * 128 + k0 + c); \
                }                                                             \
            }                                                                 \
            const float* Wc = ((ch) < 4) ? W : W2base;                        \
            int k = idx >> 5, c2 = (idx & 31) * 4;                            \
            pwv[t] = *(const float4*)(Wc + (size_t)(k0 + k) * 128 + c2);      \
        }                                                                     \
    }

#define STORE_CHUNK(XsP, WsP)                                                 \
    {                                                                         \
        _Pragma("unroll")                                                     \
        for (int t = 0; t < 4; t++) {                                         \
            int idx = tid + t * 256;                                          \
            int r = idx >> 3, c = (idx & 7) * 4;                              \
            uint4 u;                                                          \
            u.x = f2tf32(pxv[t].x); u.y = f2tf32(pxv[t].y);                   \
            u.z = f2tf32(pxv[t].z); u.w = f2tf32(pxv[t].w);                   \
            *(uint4*)&(XsP)[r * XS_STRIDE + c] = u;                           \
            int k = idx >> 5, c2 = (idx & 31) * 4;                            \
            uint4 w;                                                          \
            w.x = f2tf32(pwv[t].x); w.y = f2tf32(pwv[t].y);                   \
            w.z = f2tf32(pwv[t].z); w.w = f2tf32(pwv[t].w);                   \
            *(uint4*)&(WsP)[k * WS_STRIDE + c2] = w;                          \
        }                                                                     \
    }

    LOAD_CHUNK(0);
    STORE_CHUNK(Xs0, Ws0);
    __syncthreads();

    for (int chunk = 0; chunk < nchunks; chunk++) {
        const uint32_t* Xc = (chunk & 1) ? Xs1 : Xs0;
        const uint32_t* Wc = (chunk & 1) ? Ws1 : Ws0;
        uint32_t* Xn = (chunk & 1) ? Xs0 : Xs1;
        uint32_t* Wn = (chunk & 1) ? Ws0 : Ws1;

        if (chunk + 1 < nchunks) LOAD_CHUNK(chunk + 1);

#pragma unroll
        for (int kk = 0; kk < 4; kk++) {
            int kb = kk * 8;
            uint32_t a[2][4];
#pragma unroll
            for (int mt = 0; mt < 2; mt++) {
                int r = wm + mt * 16 + (lane >> 2);
                int c = kb + (lane & 3);
                a[mt][0] = Xc[r * XS_STRIDE + c];
                a[mt][1] = Xc[(r + 8) * XS_STRIDE + c];
                a[mt][2] = Xc[r * XS_STRIDE + c + 4];
                a[mt][3] = Xc[(r + 8) * XS_STRIDE + c + 4];
            }
#pragma unroll
            for (int nt = 0; nt < 8; nt++) {
                int col = wn + nt * 8 + (lane >> 2);
                uint32_t b0 = Wc[(kb + (lane & 3)) * WS_STRIDE + col];
                uint32_t b1 = Wc[(kb + (lane & 3) + 4) * WS_STRIDE + col];
                mma_tf32(acc[0][nt], a[0], b0, b1);
                mma_tf32(acc[1][nt], a[1], b0, b1);
            }
        }

        if (chunk + 1 < nchunks) {
            STORE_CHUNK(Xn, Wn);
            __syncthreads();
        }
    }

    float* Yf = (float*)Ybase + (size_t)g * NF;
    __half* Yh = (__half*)Ybase + (size_t)g * NF;
#pragma unroll
    for (int mt = 0; mt < 2; mt++) {
        int r0 = row0 + wm + mt * 16 + (lane >> 2);
        int r1 = r0 + 8;
#pragma unroll
        for (int nt = 0; nt < 8; nt++) {
            int cb = wn + nt * 8 + 2 * (lane & 3);
            float bx = 0.f, by = 0.f;
            if (bias) { bx = bias[cb]; by = bias[cb + 1]; }
            float ox0 = acc[mt][nt][0] + bx, oy0 = acc[mt][nt][1] + by;
            float ox1 = acc[mt][nt][2] + bx, oy1 = acc[mt][nt][3] + by;
            if (half_out) {
                if (r0 < N_) *(__half2*)(Yh + (size_t)r0 * 128 + cb) = __floats2half2_rn(ox0, oy0);
                if (r1 < N_) *(__half2*)(Yh + (size_t)r1 * 128 + cb) = __floats2half2_rn(ox1, oy1);
            } else {
                if (r0 < N_) *(float2*)(Yf + (size_t)r0 * 128 + cb) = make_float2(ox0, oy0);
                if (r1 < N_) *(float2*)(Yf + (size_t)r1 * 128 + cb) = make_float2(ox1, oy1);
            }
        }
    }
#undef LOAD_CHUNK
#undef STORE_CHUNK
}

// plain GEMM (2D grid)
__global__ void __launch_bounds__(256) gemm_tf32_k(
    const void* __restrict__ Xbase, const float* __restrict__ Wbase,
    const float* __restrict__ bbase, void* __restrict__ Ybase,
    const void* __restrict__ X2base, const float* __restrict__ W2base,
    int wstride, int bstride, int half_out, int half_in)
{
    gemm_body(blockIdx.y, blockIdx.x, Xbase, Wbase, bbase, Ybase,
              X2base, W2base, wstride, bstride, half_out, half_in);
}

// merged: GEMM ⊕ count_deg
__global__ void __launch_bounds__(256) gemm_count_k(
    const void* __restrict__ Xbase, const float* __restrict__ Wbase,
    const float* __restrict__ bbase, void* __restrict__ Ybase,
    int wstride, int bstride, int half_out, const void* __restrict__ edges)
{
    if (blockIdx.x < GEMM_BLOCKS) {
        int g = blockIdx.x / GEMM_BX;
        gemm_body(g, blockIdx.x - g * GEMM_BX, Xbase, Wbase, bbase, Ybase,
                  nullptr, nullptr, wstride, bstride, half_out, 0);
    } else {
        count_deg_body(edges, blockIdx.x - GEMM_BLOCKS);
    }
}

// merged: GEMM ⊕ fill_csr
__global__ void __launch_bounds__(256) gemm_fill_k(
    const void* __restrict__ Xbase, const float* __restrict__ Wbase,
    const float* __restrict__ bbase, void* __restrict__ Ybase,
    int wstride, int bstride, int half_out, const void* __restrict__ edges)
{
    if (blockIdx.x < GEMM_BLOCKS) {
        int g = blockIdx.x / GEMM_BX;
        gemm_body(g, blockIdx.x - g * GEMM_BX, Xbase, Wbase, bbase, Ybase,
                  nullptr, nullptr, wstride, bstride, half_out, 0);
    } else {
        fill_csr_body(edges, blockIdx.x - GEMM_BLOCKS);
    }
}

// merged: GEMM ⊕ gv_reduce
__global__ void __launch_bounds__(256) gemm_gv_k(
    const void* __restrict__ Xbase, const float* __restrict__ Wbase,
    const float* __restrict__ bbase, void* __restrict__ Ybase,
    int wstride, int bstride, int half_out)
{
    if (blockIdx.x < GEMM_BLOCKS) {
        int g = blockIdx.x / GEMM_BX;
        gemm_body(g, blockIdx.x - g * GEMM_BX, Xbase, Wbase, bbase, Ybase,
                  nullptr, nullptr, wstride, bstride, half_out, 0);
    } else {
        int j = blockIdx.x - GEMM_BLOCKS;
        int g = j / 98;
        int nb = j - g * 98;
        int f = threadIdx.x & 127;
        int half = threadIdx.x >> 7;
        int n0 = nb * 512 + half * 256;
        int nend = n0 + 256; if (nend > N_) nend = N_;
        float s = 0.f;
        const float* eg = d_enc + (size_t)g * NF;
        for (int n = n0; n < nend; n++) s += eg[(size_t)n * F_ + f];
        atomicAdd(&d_gv[g * F_ + f], s);
    }
}

// ---------------- single-source GCN aggregation ---------------------------
__global__ void aggh_k(const __half* __restrict__ hbase, float* __restrict__ out,
                       const float* __restrict__ bias)
{
    int warp = (blockIdx.x * blockDim.x + threadIdx.x) >> 5;
    int lane = threadIdx.x & 31;
    if (warp >= N_) return;
    int g = blockIdx.y;
    int node = warp;
    int c0 = lane * 4;

    const __half* hg = hbase + (size_t)g * NF;
    const float* dv = d_dinv + g * N_;
    const int* rp = d_rowptr + g * (N_ + 1);
    const int* cg = d_col + (size_t)g * E_;

    int beg = rp[node], end = rp[node + 1];
    float4 acc = make_float4(0.f, 0.f, 0.f, 0.f);
    int e = beg;
    for (; e + 4 <= end; e += 4) {
        int s0 = cg[e], s1 = cg[e + 1], s2 = cg[e + 2], s3 = cg[e + 3];
        float w0 = dv[s0], w1 = dv[s1], w2 = dv[s2], w3 = dv[s3];
        uint2 r0 = *(const uint2*)(hg + (size_t)s0 * F_ + c0);
        uint2 r1 = *(const uint2*)(hg + (size_t)s1 * F_ + c0);
        uint2 r2 = *(const uint2*)(hg + (size_t)s2 * F_ + c0);
        uint2 r3 = *(const uint2*)(hg + (size_t)s3 * F_ + c0);
        float2 a0 = __half22float2(*(__half2*)&r0.x), b0 = __half22float2(*(__half2*)&r0.y);
        float2 a1 = __half22float2(*(__half2*)&r1.x), b1 = __half22float2(*(__half2*)&r1.y);
        float2 a2 = __half22float2(*(__half2*)&r2.x), b2 = __half22float2(*(__half2*)&r2.y);
        float2 a3 = __half22float2(*(__half2*)&r3.x), b3 = __half22float2(*(__half2*)&r3.y);
        acc.x += w0 * a0.x + w1 * a1.x + w2 * a2.x + w3 * a3.x;
        acc.y += w0 * a0.y + w1 * a1.y + w2 * a2.y + w3 * a3.y;
        acc.z += w0 * b0.x + w1 * b1.x + w2 * b2.x + w3 * b3.x;
        acc.w += w0 * b0.y + w1 * b1.y + w2 * b2.y + w3 * b3.y;
    }
    for (; e < end; e++) {
        int s = cg[e];
        float w = dv[s];
        uint2 r = *(const uint2*)(hg + (size_t)s * F_ + c0);
        float2 a = __half22float2(*(__half2*)&r.x), b = __half22float2(*(__half2*)&r.y);
        acc.x += w * a.x; acc.y += w * a.y; acc.z += w * b.x; acc.w += w * b.y;
    }
    float di = dv[node];
    float di2 = di * di;
    uint2 rs = *(const uint2*)(hg + (size_t)node * F_ + c0);
    float2 sa = __half22float2(*(__half2*)&rs.x), sb = __half22float2(*(__half2*)&rs.y);
    float4 b4 = *(const float4*)(bias + c0);
    float4 o;
    o.x = di * acc.x + di2 * sa.x + b4.x;
    o.y = di * acc.y + di2 * sa.y + b4.y;
    o.z = di * acc.z + di2 * sb.x + b4.z;
    o.w = di * acc.w + di2 * sb.y + b4.w;
    *(float4*)(out + (size_t)g * NF + (size_t)node * F_ + c0) = o;
}

// ---------------- dual-source GCN aggregation + fused obf ------------------
__global__ void dual_agg_k(const __half* __restrict__ srcA_base,
                           const __half* __restrict__ srcB_base, int srcB_stride,
                           void* __restrict__ outA_base, void* __restrict__ outB_base,
                           const float* __restrict__ bias,
                           const float* __restrict__ cmp_base,
                           int part_base, int oth_mode, int out_half)
{
    __shared__ float sobf[8];
    int tid = threadIdx.x;
    int warp = (blockIdx.x * blockDim.x + tid) >> 5;
    int lane = tid & 31;
    int wid = tid >> 5;
    int g = blockIdx.y;
    int c0 = lane * 4;
    float obf = 0.f;

    if (warp < N_) {
        int node = warp;
        const __half* hA = srcA_base + (size_t)g * NF;
        const __half* hB = srcB_base + (size_t)g * srcB_stride;
        const float* dv = d_dinv + g * N_;
        const int* rp = d_rowptr + g * (N_ + 1);
        const int* cg = d_col + (size_t)g * E_;

        int beg = rp[node], end = rp[node + 1];
        float4 accA = make_float4(0.f, 0.f, 0.f, 0.f);
        float4 accB = make_float4(0.f, 0.f, 0.f, 0.f);
        int e = beg;
        for (; e + 4 <= end; e += 4) {
            int s0 = cg[e], s1 = cg[e + 1], s2 = cg[e + 2], s3 = cg[e + 3];
            float w0 = dv[s0], w1 = dv[s1], w2 = dv[s2], w3 = dv[s3];
            uint2 a0 = *(const uint2*)(hA + (size_t)s0 * F_ + c0);
            uint2 a1 = *(const uint2*)(hA + (size_t)s1 * F_ + c0);
            uint2 a2 = *(const uint2*)(hA + (size_t)s2 * F_ + c0);
            uint2 a3 = *(const uint2*)(hA + (size_t)s3 * F_ + c0);
            uint2 b0 = *(const uint2*)(hB + (size_t)s0 * F_ + c0);
            uint2 b1 = *(const uint2*)(hB + (size_t)s1 * F_ + c0);
            uint2 b2 = *(const uint2*)(hB + (size_t)s2 * F_ + c0);
            uint2 b3 = *(const uint2*)(hB + (size_t)s3 * F_ + c0);
            float2 ax0 = __half22float2(*(__half2*)&a0.x), az0 = __half22float2(*(__half2*)&a0.y);
            float2 ax1 = __half22float2(*(__half2*)&a1.x), az1 = __half22float2(*(__half2*)&a1.y);
            float2 ax2 = __half22float2(*(__half2*)&a2.x), az2 = __half22float2(*(__half2*)&a2.y);
            float2 ax3 = __half22float2(*(__half2*)&a3.x), az3 = __half22float2(*(__half2*)&a3.y);
            float2 bx0 = __half22float2(*(__half2*)&b0.x), bz0 = __half22float2(*(__half2*)&b0.y);
            float2 bx1 = __half22float2(*(__half2*)&b1.x), bz1 = __half22float2(*(__half2*)&b1.y);
            float2 bx2 = __half22float2(*(__half2*)&b2.x), bz2 = __half22float2(*(__half2*)&b2.y);
            float2 bx3 = __half22float2(*(__half2*)&b3.x), bz3 = __half22float2(*(__half2*)&b3.y);
            accA.x += w0 * ax0.x + w1 * ax1.x + w2 * ax2.x + w3 * ax3.x;
            accA.y += w0 * ax0.y + w1 * ax1.y + w2 * ax2.y + w3 * ax3.y;
            accA.z += w0 * az0.x + w1 * az1.x + w2 * az2.x + w3 * az3.x;
            accA.w += w0 * az0.y + w1 * az1.y + w2 * az2.y + w3 * az3.y;
            accB.x += w0 * bx0.x + w1 * bx1.x + w2 * bx2.x + w3 * bx3.x;
            accB.y += w0 * bx0.y + w1 * bx1.y + w2 * bx2.y + w3 * bx3.y;
            accB.z += w0 * bz0.x + w1 * bz1.x + w2 * bz2.x + w3 * bz3.x;
            accB.w += w0 * bz0.y + w1 * bz1.y + w2 * bz2.y + w3 * bz3.y;
        }
        for (; e < end; e++) {
            int s = cg[e];
            float w = dv[s];
            uint2 a = *(const uint2*)(hA + (size_t)s * F_ + c0);
            uint2 b = *(const uint2*)(hB + (size_t)s * F_ + c0);
            float2 ax = __half22float2(*(__half2*)&a.x), az = __half22float2(*(__half2*)&a.y);
            float2 bx = __half22float2(*(__half2*)&b.x), bz = __half22float2(*(__half2*)&b.y);
            accA.x += w * ax.x; accA.y += w * ax.y; accA.z += w * az.x; accA.w += w * az.y;
            accB.x += w * bx.x; accB.y += w * bx.y; accB.z += w * bz.x; accB.w += w * bz.y;
        }
        float di = dv[node];
        float di2 = di * di;
        uint2 ra = *(const uint2*)(hA + (size_t)node * F_ + c0);
        uint2 rb = *(const uint2*)(hB + (size_t)node * F_ + c0);
        float2 sax = __half22float2(*(__half2*)&ra.x), saz = __half22float2(*(__half2*)&ra.y);
        float2 sbx = __half22float2(*(__half2*)&rb.x), sbz = __half22float2(*(__half2*)&rb.y);
        float4 b4 = *(const float4*)(bias + c0);

        float4 A;
        A.x = di * accA.x + di2 * sax.x;
        A.y = di * accA.y + di2 * sax.y;
        A.z = di * accA.z + di2 * saz.x;
        A.w = di * accA.w + di2 * saz.y;
        float4 B;
        B.x = di * accB.x + di2 * sbx.x;
        B.y = di * accB.y + di2 * sbx.y;
        B.z = di * accB.z + di2 * sbz.x;
        B.w = di * accB.w + di2 * sbz.y;

        float4 oA = make_float4(A.x + b4.x, A.y + b4.y, A.z + b4.z, A.w + b4.w);
        float4 oB;
        if (oth_mode) {
            oB.x = 0.5f * (B.x - A.x) + b4.x;
            oB.y = 0.5f * (B.y - A.y) + b4.y;
            oB.z = 0.5f * (B.z - A.z) + b4.z;
            oB.w = 0.5f * (B.w - A.w) + b4.w;
        } else {
            oB = make_float4(B.x + b4.x, B.y + b4.y, B.z + b4.z, B.w + b4.w);
        }
        size_t off = (size_t)g * NF + (size_t)node * F_ + c0;
        if (out_half) {
            __half* oAp = (__half*)outA_base + off;
            __half* oBp = (__half*)outB_base + off;
            *(__half2*)oAp = __floats2half2_rn(oA.x, oA.y);
            *(__half2*)(oAp + 2) = __floats2half2_rn(oA.z, oA.w);
            *(__half2*)oBp = __floats2half2_rn(oB.x, oB.y);
            *(__half2*)(oBp + 2) = __floats2half2_rn(oB.z, oB.w);
        } else {
            *(float4*)((float*)outA_base + off) = oA;
            *(float4*)((float*)outB_base + off) = oB;
        }

        float4 cm = *(const float4*)(cmp_base + off);
        float dx = cm.x - oA.x, dy = cm.y - oA.y, dz = cm.z - oA.z, dw = cm.w - oA.w;
        obf = dx * dx + dy * dy + dz * dz + dw * dw;
    }

#pragma unroll
    for (int off = 16; off; off >>= 1) obf += __shfl_xor_sync(0xFFFFFFFFu, obf, off);
    if (lane == 0) sobf[wid] = obf;
    __syncthreads();
    if (tid == 0) {
        float s = 0.f;
#pragma unroll
        for (int w = 0; w < 8; w++) s += sobf[w];
        atomicAdd(&d_parts[part_base + g], s);
    }
}

// ------------------------- sum3 ⊕ compute_u ---------------------------------
__global__ void sum3_u_k(const float* __restrict__ att) {
    if (blockIdx.x < U_BLOCKS) {
        int g = blockIdx.x;
        int dcol = threadIdx.x;
        __shared__ float sv[F_];
        if (dcol < F_) {
            float m = d_gv[g * F_ + dcol] * (1.f / (float)N_);
            sv[dcol] = 1.f / (1.f + expf(-m));
        }
        __syncthreads();
        if (dcol < F_) {
            const float* row = att + ((size_t)g * F_ + dcol) * F_;
            float s = 0.f;
#pragma unroll 4
            for (int e = 0; e < F_; e++) s += row[e] * sv[e];
            d_u[g * F_ + dcol] = s;
        }
    } else {
        size_t i = (size_t)(blockIdx.x - U_BLOCKS) * blockDim.x + threadIdx.x;
        size_t H = NF / 2;
        if (i >= H) return;
        const __half2* h = (const __half2*)d_htmp;
        float2 a = __half22float2(h[i]);
        float2 b = __half22float2(h[H + i]);
        float2 c = __half22float2(h[2 * H + i]);
        ((__half2*)d_hS1)[i] = __floats2half2_rn(a.x + b.x + c.x, a.y + b.y + c.y);
    }
}

// ---------- fuse_feat + used_feat + comp_re + efin obf + finalize ----------
__global__ void fuse_comp_k(float* __restrict__ out) {
    __shared__ __align__(16) float su[G_ * F_];
    __shared__ float sred[3][8];
    int tid = threadIdx.x;
    int lane = tid & 31;
    int wid = tid >> 5;
    for (int i = tid; i < G_ * F_; i += blockDim.x) su[i] = d_u[i];
    __syncthreads();

    int node = blockIdx.x * 8 + wid;
    float l01 = 0.f, l02 = 0.f, l12 = 0.f;

    if (node < N_) {
        float4 e[G_];
#pragma unroll
        for (int j = 0; j < G_; j++)
            e[j] = *(const float4*)(d_enc + (size_t)j * NF + (size_t)node * F_ + lane * 4);
        {
            float4 o;
            float mx = (e[0].x + e[1].x + e[2].x) * (1.f / 3.f);
            float my = (e[0].y + e[1].y + e[2].y) * (1.f / 3.f);
            float mz = (e[0].z + e[1].z + e[2].z) * (1.f / 3.f);
            float mw = (e[0].w + e[1].w + e[2].w) * (1.f / 3.f);
            o.x = (mx > 0.f) ? mx : expm1f(mx);
            o.y = (my > 0.f) ? my : expm1f(my);
            o.z = (mz > 0.f) ? mz : expm1f(mz);
            o.w = (mw > 0.f) ? mw : expm1f(mw);
            *(float4*)(out + NF + (size_t)node * F_ + lane * 4) = o;
        }
        float dots[G_][G_];
#pragma unroll
        for (int i = 0; i < G_; i++) {
            float4 uu = *(const float4*)&su[i * F_ + lane * 4];
#pragma unroll
            for (int j = 0; j < G_; j++) {
                float p = e[j].x * uu.x + e[j].y * uu.y + e[j].z * uu.z + e[j].w * uu.w;
#pragma unroll
                for (int off = 16; off; off >>= 1) p += __shfl_xor_sync(0xFFFFFFFFu, p, off);
                dots[i][j] = p;
            }
        }
        if (lane == 0) {
            float* cb = out + 2 * NF;
#pragma unroll
            for (int i = 0; i < G_; i++) {
                float s[G_], tot = 0.f;
#pragma unroll
                for (int j = 0; j < G_; j++) { s[j] = 1.f / (1.f + expf(-dots[i][j])); tot += s[j]; }
                float inv = 1.f / tot;
#pragma unroll
                for (int j = 0; j < G_; j++) cb[(size_t)node * 9 + i * 3 + j] = s[j] * inv;
            }
        }
        float4 f[G_];
#pragma unroll
        for (int j = 0; j < G_; j++)
            f[j] = *(const float4*)(d_efin + (size_t)j * NF + (size_t)node * F_ + lane * 4);
        {
            float4 o;
            float mx = (f[0].x + f[1].x + f[2].x) * (1.f / 3.f);
            float my = (f[0].y + f[1].y + f[2].y) * (1.f / 3.f);
            float mz = (f[0].z + f[1].z + f[2].z) * (1.f / 3.f);
            float mw = (f[0].w + f[1].w + f[2].w) * (1.f / 3.f);
            o.x = 1.f / (1.f + expf(-mx));
            o.y = 1.f / (1.f + expf(-my));
            o.z = 1.f / (1.f + expf(-mz));
            o.w = 1.f / (1.f + expf(-mw));
            *(float4*)(out + (size_t)node * F_ + lane * 4) = o;
        }
        {
            float dx, dy, dz, dw;
            dx = f[0].x - f[1].x; dy = f[0].y - f[1].y; dz = f[0].z - f[1].z; dw = f[0].w - f[1].w;
            l01 = dx * dx + dy * dy + dz * dz + dw * dw;
            dx = f[0].x - f[2].x; dy = f[0].y - f[2].y; dz = f[0].z - f[2].z; dw = f[0].w - f[2].w;
            l02 = dx * dx + dy * dy + dz * dz + dw * dw;
            dx = f[1].x - f[2].x; dy = f[1].y - f[2].y; dz = f[1].z - f[2].z; dw = f[1].w - f[2].w;
            l12 = dx * dx + dy * dy + dz * dz + dw * dw;
        }
    }

#pragma unroll
    for (int off = 16; off; off >>= 1) {
        l01 += __shfl_xor_sync(0xFFFFFFFFu, l01, off);
        l02 += __shfl_xor_sync(0xFFFFFFFFu, l02, off);
        l12 += __shfl_xor_sync(0xFFFFFFFFu, l12, off);
    }
    if (lane == 0) { sred[0][wid] = l01; sred[1][wid] = l02; sred[2][wid] = l12; }
    __syncthreads();

    __shared__ int slast;
    if (tid == 0) {
        float a = 0.f, b = 0.f, c = 0.f;
#pragma unroll
        for (int w = 0; w < 8; w++) { a += sred[0][w]; b += sred[1][w]; c += sred[2][w]; }
        atomicAdd(&d_parts[6], a);
        atomicAdd(&d_parts[7], b);
        atomicAdd(&d_parts[8], c);
        __threadfence();
        slast = (atomicAdd(&d_done, 1) == FUSE_BLOCKS - 1);
    }
    __syncthreads();
    if (slast && tid == 0) {
        float obf1 = 0.f;
#pragma unroll
        for (int g = 0; g < G_; g++)
            obf1 += 0.5f * (sqrtf(d_parts[g]) + sqrtf(d_parts[3 + g]));
        float obf0 = 2.f * (sqrtf(d_parts[6]) + sqrtf(d_parts[7]) + sqrtf(d_parts[8]));
        out[2 * NF + 9 * (size_t)N_]     = obf1;
        out[2 * NF + 9 * (size_t)N_ + 1] = obf0;
    }
}

// ------------------------- host launcher -----------------------------------
extern "C" void kernel_launch(void* const* d_in, const int* in_sizes, int n_in,
                              void* d_out, int out_size)
{
    const float* x       = (const float*)d_in[0];
    const float* fc1_w   = (const float*)d_in[1];
    const float* fc1_b   = (const float*)d_in[2];
    const float* w_conv1 = (const float*)d_in[3];
    const float* b_conv1 = (const float*)d_in[4];
    const float* w_conv2 = (const float*)d_in[5];
    const float* b_conv2 = (const float*)d_in[6];
    const float* w_dconv1 = (const float*)d_in[7];
    const float* b_dconv1 = (const float*)d_in[8];
    const float* w_dconv2 = (const float*)d_in[9];
    const float* b_dconv2 = (const float*)d_in[10];
    const float* fc2_w   = (const float*)d_in[11];
    const float* fc2_b   = (const float*)d_in[12];
    const float* att_w   = (const float*)d_in[13];
    const void*  edges   = (const void*)d_in[14];
    float* out = (float*)d_out;

    float *pre, *conv1, *enc, *efin;
    __half *htmp, *h6, *hS1, *ow1h, *own2h, *oth2h;
    cudaGetSymbolAddress((void**)&pre,   d_pre);
    cudaGetSymbolAddress((void**)&conv1, d_conv1);
    cudaGetSymbolAddress((void**)&enc,   d_enc);
    cudaGetSymbolAddress((void**)&efin,  d_efin);
    cudaGetSymbolAddress((void**)&htmp,  d_htmp);
    cudaGetSymbolAddress((void**)&h6,    d_h6);
    cudaGetSymbolAddress((void**)&hS1,   d_hS1);
    cudaGetSymbolAddress((void**)&ow1h,  d_ow1h);
    cudaGetSymbolAddress((void**)&own2h, d_own2h);
    cudaGetSymbolAddress((void**)&oth2h, d_oth2h);

    cudaFuncSetAttribute(gemm_tf32_k,  cudaFuncAttributeMaxDynamicSharedMemorySize, GEMM_SMEM_BYTES);
    cudaFuncSetAttribute(gemm_count_k, cudaFuncAttributeMaxDynamicSharedMemorySize, GEMM_SMEM_BYTES);
    cudaFuncSetAttribute(gemm_fill_k,  cudaFuncAttributeMaxDynamicSharedMemorySize, GEMM_SMEM_BYTES);
    cudaFuncSetAttribute(gemm_gv_k,    cudaFuncAttributeMaxDynamicSharedMemorySize, GEMM_SMEM_BYTES);

    const int TB = 256;
    dim3 gemm_grid(GEMM_BX, G_);
    dim3 gemm_grid6(GEMM_BX, 2 * G_);
    dim3 agg_grid((N_ + 7) / 8, G_);
    dim3 scan_grid(SB_, G_);

    // L1: detect dtype ⊕ zero
    detect_zero_k<<<1 + (G_ * N_ + TB - 1) / TB, TB>>>(edges);
    // L2: fc1 GEMM ⊕ count_deg
    gemm_count_k<<<GEMM_BLOCKS + CSRB, TB, GEMM_SMEM_BYTES>>>(x, fc1_w, fc1_b, pre,
                                                              F_ * F_, F_, 0, edges);
    // L3-L4: scan
    scan_p1_k<<<scan_grid, TB>>>();
    scan_p3_k<<<scan_grid, TB>>>();
    // L5: conv1 GEMM ⊕ fill_csr
    gemm_fill_k<<<GEMM_BLOCKS + CSRB, TB, GEMM_SMEM_BYTES>>>(pre, w_conv1, nullptr, htmp,
                                                             0, 0, 1, edges);
    // L6: agg -> conv1
    aggh_k<<<agg_grid, TB>>>(htmp, conv1, b_conv1);
    // L7: conv2 GEMM
    gemm_tf32_k<<<gemm_grid, TB, GEMM_SMEM_BYTES>>>(conv1, w_conv2, nullptr, htmp,
                                                    nullptr, nullptr, 0, 0, 1, 0);
    // L8: agg -> enc
    aggh_k<<<agg_grid, TB>>>(htmp, enc, b_conv2);
    // L9: t1 GEMM ⊕ gv_reduce
    gemm_gv_k<<<GEMM_BLOCKS + GV_BLOCKS, TB, GEMM_SMEM_BYTES>>>(enc, w_dconv1, nullptr, htmp, 0, 0, 1);
    // L10: sum3 ⊕ compute_u
    sum3_u_k<<<U_BLOCKS + SUM3_BLOCKS, TB>>>(att_w);
    // L11: level-1 dual agg (own1|oth1, fp16 out) + obf(conv1-own1)
    dual_agg_k<<<agg_grid, TB>>>(htmp, hS1, 0, ow1h, ow1h + G_ * NF, b_dconv1, conv1, 3, 1, 1);
    // L12: level-2 GEMM (6 slices, fp16 in)
    gemm_tf32_k<<<gemm_grid6, TB, GEMM_SMEM_BYTES>>>(ow1h, w_dconv2, nullptr, h6,
                                                     nullptr, nullptr, 0, 0, 1, 1);
    // L13: level-2 dual agg (own2|oth2, fp16 out) + obf(pre-own2)
    dual_agg_k<<<agg_grid, TB>>>(h6, h6 + G_ * NF, NF, own2h, oth2h, b_dconv2, pre, 0, 0, 1);
    // L14: fc2 GEMM (K=256 fused, fp16 in)
    gemm_tf32_k<<<gemm_grid, TB, GEMM_SMEM_BYTES>>>(own2h, fc2_w, fc2_b, efin,
                                                    oth2h, fc2_w + F_ * F_, 0, 0, 0, 1);
    // L15: outputs (+fused finalize)
    fuse_comp_k<<<FUSE_BLOCKS, TB>>>(out);
}

// round 14
// speedup vs baseline: 1.1241x; 1.1241x over previous
#include <cuda_runtime.h>
#include <cuda_fp16.h>
#include <math.h>
#include <stdint.h>

#define N_ 50000
#define F_ 128
#define G_ 3
#define E_ 600000
#define NF ((size_t)N_ * F_)
#define SB_ 49
#define GEMM_BX 391
#define GEMM_BLOCKS (G_ * GEMM_BX)
#define CSRB 256
#define GV_BLOCKS (98 * G_)
#define U_BLOCKS G_
#define SUM3_BLOCKS ((int)((NF / 2 + 255) / 256))
#define FUSE_BLOCKS ((N_ + 7) / 8)

// fp16 GEMM smem layout (halves)
#define XSH 40                    // 32 data + 8 pad per X row
#define WSH 136                   // 128 data + 8 pad per W row
#define XS_HALVES (128 * XSH)     // 5120
#define WS_HALVES (32 * WSH)      // 4352

// ------------------------- static device scratch -------------------------
__device__ __align__(16) float d_pre  [G_ * N_ * F_];
__device__ __align__(16) float d_conv1[G_ * N_ * F_];
__device__ __align__(16) float d_enc  [G_ * N_ * F_];
__device__ __align__(16) float d_own2 [G_ * N_ * F_];
__device__ __align__(16) float d_oth2 [G_ * N_ * F_];
__device__ __align__(16) float d_ow1  [2 * G_ * N_ * F_];
__device__ __align__(16) float d_efin [G_ * N_ * F_];
__device__ __align__(16) __half d_htmp[G_ * N_ * F_];
__device__ __align__(16) __half d_h6  [2 * G_ * N_ * F_];
__device__ __align__(16) __half d_hS1 [N_ * F_];

__device__ int   d_deg   [G_ * N_];
__device__ int   d_rowptr[G_ * (N_ + 1)];
__device__ int   d_cur   [G_ * N_];
__device__ int   d_col   [G_ * E_];
__device__ int   d_bsum  [G_ * SB_];
__device__ __align__(16) float d_dinv  [G_ * N_];
__device__ float d_gv    [G_ * F_];
__device__ __align__(16) float d_u     [G_ * F_];
__device__ float d_parts [16];
__device__ int   d_e64;
__device__ int   d_done;

// ------------------------- edge load helper -------------------------------
__device__ __forceinline__ int load_edge(const void* edges, size_t idx, int e64) {
    if (e64) return (int)((const long long*)edges)[idx];
    return ((const int*)edges)[idx];
}

// ------------------------- L1: detect dtype + zero -------------------------
__global__ void detect_zero_k(const void* __restrict__ edges) {
    if (blockIdx.x == 0) {
        const unsigned int* w = (const unsigned int*)edges;
        __shared__ int any;
        if (threadIdx.x == 0) any = 0;
        __syncthreads();
        for (int i = threadIdx.x; i < 2048; i += blockDim.x)
            if (w[2 * i + 1] != 0u) any = 1;
        __syncthreads();
        if (threadIdx.x == 0) { d_e64 = any ? 0 : 1; d_done = 0; }
    } else {
        int i = (blockIdx.x - 1) * blockDim.x + threadIdx.x;
        if (i < G_ * N_) d_deg[i] = 0;
        if (i < G_ * F_) d_gv[i] = 0.f;
        if (i < 16) d_parts[i] = 0.f;
    }
}

// ------------------------- grid-strided CSR bodies -------------------------
__device__ __forceinline__ void count_deg_body(const void* edges, int bx) {
    int e64 = d_e64;
    for (int i = bx * 256 + threadIdx.x; i < G_ * E_; i += CSRB * 256) {
        int g = i / E_, e = i - g * E_;
        int dst = load_edge(edges, (size_t)g * 2 * E_ + E_ + e, e64);
        atomicAdd(&d_deg[g * N_ + dst], 1);
    }
}

__device__ __forceinline__ void fill_csr_body(const void* edges, int bx) {
    int e64 = d_e64;
    for (int i = bx * 256 + threadIdx.x; i < G_ * E_; i += CSRB * 256) {
        int g = i / E_, e = i - g * E_;
        int src = load_edge(edges, (size_t)g * 2 * E_ + e, e64);
        int dst = load_edge(edges, (size_t)g * 2 * E_ + E_ + e, e64);
        int pos = atomicAdd(&d_cur[g * N_ + dst], 1);
        d_col[(size_t)g * E_ + pos] = src;
    }
}

// --- 2-phase multi-block prefix scan (+ dinv + cur fused) ---
__global__ void scan_p1_k() {
    int g = blockIdx.y, b = blockIdx.x;
    int tid = threadIdx.x;
    int base = b * 1024 + tid * 4;
    int v = 0;
#pragma unroll
    for (int j = 0; j < 4; j++) {
        int idx = base + j;
        if (idx < N_) v += d_deg[g * N_ + idx];
    }
    __shared__ int red[256];
    red[tid] = v;
    __syncthreads();
    for (int s = 128; s > 0; s >>= 1) {
        if (tid < s) red[tid] += red[tid + s];
        __syncthreads();
    }
    if (tid == 0) d_bsum[g * SB_ + b] = red[0];
}

__global__ void scan_p3_k() {
    int g = blockIdx.y, b = blockIdx.x;
    int tid = threadIdx.x;
    __shared__ int soff;
    if (tid == 0) {
        int acc = 0;
        for (int i = 0; i < b; i++) acc += d_bsum[g * SB_ + i];
        soff = acc;
    }
    int base = b * 1024 + tid * 4;
    int v[4]; int s = 0;
#pragma unroll
    for (int j = 0; j < 4; j++) {
        int idx = base + j;
        v[j] = (idx < N_) ? d_deg[g * N_ + idx] : 0;
        s += v[j];
    }
    __shared__ int sc[256];
    sc[tid] = s;
    __syncthreads();
    for (int st = 1; st < 256; st <<= 1) {
        int t = (tid >= st) ? sc[tid - st] : 0;
        __syncthreads();
        sc[tid] += t;
        __syncthreads();
    }
    int run = soff + sc[tid] - s;
    if (b == 0 && tid == 0) d_rowptr[g * (N_ + 1)] = 0;
#pragma unroll
    for (int j = 0; j < 4; j++) {
        int idx = base + j;
        if (idx < N_) {
            d_cur[g * N_ + idx] = run;
            run += v[j];
            d_rowptr[g * (N_ + 1) + idx + 1] = run;
            d_dinv[g * N_ + idx] = rsqrtf((float)(v[j] + 1));
        }
    }
}

// ------------------------- fp16 tensor-core GEMM ---------------------------
__device__ __forceinline__ uint32_t smem_u32(const void* p) {
    return (uint32_t)__cvta_generic_to_shared(p);
}

__device__ __forceinline__ void ldmat_x4(uint32_t* r, uint32_t addr) {
    asm volatile("ldmatrix.sync.aligned.m8n8.x4.shared.b16 {%0,%1,%2,%3}, [%4];"
        : "=r"(r[0]), "=r"(r[1]), "=r"(r[2]), "=r"(r[3]) : "r"(addr));
}

__device__ __forceinline__ void ldmat_x4t(uint32_t* r, uint32_t addr) {
    asm volatile("ldmatrix.sync.aligned.m8n8.x4.trans.shared.b16 {%0,%1,%2,%3}, [%4];"
        : "=r"(r[0]), "=r"(r[1]), "=r"(r[2]), "=r"(r[3]) : "r"(addr));
}

__device__ __forceinline__ void mma_f16(float* c, const uint32_t* a,
                                        uint32_t b0, uint32_t b1) {
    asm volatile(
        "mma.sync.aligned.m16n8k16.row.col.f32.f16.f16.f32 "
        "{%0,%1,%2,%3}, {%4,%5,%6,%7}, {%8,%9}, {%0,%1,%2,%3};"
        : "+f"(c[0]), "+f"(c[1]), "+f"(c[2]), "+f"(c[3])
        : "r"(a[0]), "r"(a[1]), "r"(a[2]), "r"(a[3]), "r"(b0), "r"(b1));
}

__device__ __forceinline__ void gemm_body(
    int g, int rb,
    const float* __restrict__ Xbase, const float* __restrict__ Wbase,
    const float* __restrict__ bbase, void* __restrict__ Ybase,
    const float* __restrict__ X2base, const float* __restrict__ W2base,
    int wstride, int bstride, int half_out)
{
    const float* X  = Xbase + (size_t)g * NF;
    const float* W  = Wbase + (size_t)g * wstride;
    const float* X2 = X2base ? (X2base + (size_t)g * NF) : nullptr;
    const float* bias = bbase ? (bbase + (size_t)g * bstride) : nullptr;
    int row0 = rb * 128;

    __shared__ __align__(16) __half sX[2][XS_HALVES];
    __shared__ __align__(16) __half sW[2][WS_HALVES];

    int tid = threadIdx.x;
    int lane = tid & 31;
    int wid = tid >> 5;
    int wm = (wid >> 1) * 32;
    int wn = (wid & 1) * 64;

    float acc[2][8][4];
#pragma unroll
    for (int mt = 0; mt < 2; mt++)
#pragma unroll
        for (int nt = 0; nt < 8; nt++)
#pragma unroll
            for (int q = 0; q < 4; q++) acc[mt][nt][q] = 0.f;

    int nchunks = X2 ? 8 : 4;

    // per-lane ldmatrix byte offsets (within a buffer)
    int lrow = (lane & 7) + ((lane & 8) ? 8 : 0);
    int seg8 = (lane & 16) ? 8 : 0;                 // k-seg for A, n-seg for B
    uint32_t offA = (uint32_t)(((wm + lrow) * XSH + seg8) * 2);
    uint32_t offB = (uint32_t)((lrow * WSH + wn + seg8) * 2);
    uint32_t baseX[2] = { smem_u32(sX[0]), smem_u32(sX[1]) };
    uint32_t baseW[2] = { smem_u32(sW[0]), smem_u32(sW[1]) };

    float4 pxv[4], pwv[4];
#define LOAD_CHUNK(ch)                                                        \
    {                                                                         \
        const float* Xc = ((ch) < 4) ? X : X2;                                \
        const float* Wc = ((ch) < 4) ? W : W2base;                            \
        int k0 = ((ch) & 3) * 32;                                             \
        _Pragma("unroll")                                                     \
        for (int t = 0; t < 4; t++) {                                         \
            int idx = tid + t * 256;                                          \
            int r = idx >> 3, c = (idx & 7) * 4;                              \
            int row = row0 + r;                                               \
            pxv[t] = make_float4(0.f, 0.f, 0.f, 0.f);                         \
            if (row < N_) pxv[t] = *(const float4*)(Xc + (size_t)row * 128 + k0 + c); \
            int k = idx >> 5, c2 = (idx & 31) * 4;                            \
            pwv[t] = *(const float4*)(Wc + (size_t)(k0 + k) * 128 + c2);      \
        }                                                                     \
    }

#define STORE_CHUNK(bi)                                                       \
    {                                                                         \
        _Pragma("unroll")                                                     \
        for (int t = 0; t < 4; t++) {                                         \
            int idx = tid + t * 256;                                          \
            int r = idx >> 3, c = (idx & 7) * 4;                              \
            *(__half2*)&sX[bi][r * XSH + c]     = __floats2half2_rn(pxv[t].x, pxv[t].y); \
            *(__half2*)&sX[bi][r * XSH + c + 2] = __floats2half2_rn(pxv[t].z, pxv[t].w); \
            int k = idx >> 5, c2 = (idx & 31) * 4;                            \
            *(__half2*)&sW[bi][k * WSH + c2]     = __floats2half2_rn(pwv[t].x, pwv[t].y); \
            *(__half2*)&sW[bi][k * WSH + c2 + 2] = __floats2half2_rn(pwv[t].z, pwv[t].w); \
        }                                                                     \
    }

    LOAD_CHUNK(0);
    STORE_CHUNK(0);
    __syncthreads();

    for (int chunk = 0; chunk < nchunks; chunk++) {
        int bi = chunk & 1;
        if (chunk + 1 < nchunks) LOAD_CHUNK(chunk + 1);

#pragma unroll
        for (int s = 0; s < 2; s++) {
            uint32_t a0[4], a1[4];
            ldmat_x4(a0, baseX[bi] + offA + (uint32_t)((s * 16) * 2));
            ldmat_x4(a1, baseX[bi] + offA + (uint32_t)((16 * XSH + s * 16) * 2));
#pragma unroll
            for (int ntp = 0; ntp < 4; ntp++) {
                uint32_t b[4];
                ldmat_x4t(b, baseW[bi] + offB + (uint32_t)((s * 16 * WSH + ntp * 16) * 2));
                mma_f16(acc[0][2 * ntp],     a0, b[0], b[1]);
                mma_f16(acc[1][2 * ntp],     a1, b[0], b[1]);
                mma_f16(acc[0][2 * ntp + 1], a0, b[2], b[3]);
                mma_f16(acc[1][2 * ntp + 1], a1, b[2], b[3]);
            }
        }

        if (chunk + 1 < nchunks) {
            STORE_CHUNK(bi ^ 1);
            __syncthreads();
        }
    }

    float* Yf = (float*)Ybase + (size_t)g * NF;
    __half* Yh = (__half*)Ybase + (size_t)g * NF;
#pragma unroll
    for (int mt = 0; mt < 2; mt++) {
        int r0 = row0 + wm + mt * 16 + (lane >> 2);
        int r1 = r0 + 8;
#pragma unroll
        for (int nt = 0; nt < 8; nt++) {
            int cb = wn + nt * 8 + 2 * (lane & 3);
            float bx = 0.f, by = 0.f;
            if (bias) { bx = bias[cb]; by = bias[cb + 1]; }
            float ox0 = acc[mt][nt][0] + bx, oy0 = acc[mt][nt][1] + by;
            float ox1 = acc[mt][nt][2] + bx, oy1 = acc[mt][nt][3] + by;
            if (half_out) {
                if (r0 < N_) *(__half2*)(Yh + (size_t)r0 * 128 + cb) = __floats2half2_rn(ox0, oy0);
                if (r1 < N_) *(__half2*)(Yh + (size_t)r1 * 128 + cb) = __floats2half2_rn(ox1, oy1);
            } else {
                if (r0 < N_) *(float2*)(Yf + (size_t)r0 * 128 + cb) = make_float2(ox0, oy0);
                if (r1 < N_) *(float2*)(Yf + (size_t)r1 * 128 + cb) = make_float2(ox1, oy1);
            }
        }
    }
#undef LOAD_CHUNK
#undef STORE_CHUNK
}

// plain GEMM (2D grid)
__global__ void __launch_bounds__(256) gemm_tf32_k(
    const float* __restrict__ Xbase, const float* __restrict__ Wbase,
    const float* __restrict__ bbase, void* __restrict__ Ybase,
    const float* __restrict__ X2base, const float* __restrict__ W2base,
    int wstride, int bstride, int half_out)
{
    gemm_body(blockIdx.y, blockIdx.x, Xbase, Wbase, bbase, Ybase,
              X2base, W2base, wstride, bstride, half_out);
}

// merged: GEMM ⊕ count_deg
__global__ void __launch_bounds__(256) gemm_count_k(
    const float* __restrict__ Xbase, const float* __restrict__ Wbase,
    const float* __restrict__ bbase, void* __restrict__ Ybase,
    int wstride, int bstride, int half_out, const void* __restrict__ edges)
{
    if (blockIdx.x < GEMM_BLOCKS) {
        int g = blockIdx.x / GEMM_BX;
        gemm_body(g, blockIdx.x - g * GEMM_BX, Xbase, Wbase, bbase, Ybase,
                  nullptr, nullptr, wstride, bstride, half_out);
    } else {
        count_deg_body(edges, blockIdx.x - GEMM_BLOCKS);
    }
}

// merged: GEMM ⊕ fill_csr
__global__ void __launch_bounds__(256) gemm_fill_k(
    const float* __restrict__ Xbase, const float* __restrict__ Wbase,
    const float* __restrict__ bbase, void* __restrict__ Ybase,
    int wstride, int bstride, int half_out, const void* __restrict__ edges)
{
    if (blockIdx.x < GEMM_BLOCKS) {
        int g = blockIdx.x / GEMM_BX;
        gemm_body(g, blockIdx.x - g * GEMM_BX, Xbase, Wbase, bbase, Ybase,
                  nullptr, nullptr, wstride, bstride, half_out);
    } else {
        fill_csr_body(edges, blockIdx.x - GEMM_BLOCKS);
    }
}

// merged: GEMM ⊕ gv_reduce
__global__ void __launch_bounds__(256) gemm_gv_k(
    const float* __restrict__ Xbase, const float* __restrict__ Wbase,
    const float* __restrict__ bbase, void* __restrict__ Ybase,
    int wstride, int bstride, int half_out)
{
    if (blockIdx.x < GEMM_BLOCKS) {
        int g = blockIdx.x / GEMM_BX;
        gemm_body(g, blockIdx.x - g * GEMM_BX, Xbase, Wbase, bbase, Ybase,
                  nullptr, nullptr, wstride, bstride, half_out);
    } else {
        int j = blockIdx.x - GEMM_BLOCKS;
        int g = j / 98;
        int nb = j - g * 98;
        int f = threadIdx.x & 127;
        int half = threadIdx.x >> 7;
        int n0 = nb * 512 + half * 256;
        int nend = n0 + 256; if (nend > N_) nend = N_;
        float s = 0.f;
        const float* eg = d_enc + (size_t)g * NF;
        for (int n = n0; n < nend; n++) s += eg[(size_t)n * F_ + f];
        atomicAdd(&d_gv[g * F_ + f], s);
    }
}

// ---------------- single-source GCN aggregation ---------------------------
__global__ void aggh_k(const __half* __restrict__ hbase, float* __restrict__ out,
                       const float* __restrict__ bias)
{
    int warp = (blockIdx.x * blockDim.x + threadIdx.x) >> 5;
    int lane = threadIdx.x & 31;
    if (warp >= N_) return;
    int g = blockIdx.y;
    int node = warp;
    int c0 = lane * 4;

    const __half* hg = hbase + (size_t)g * NF;
    const float* dv = d_dinv + g * N_;
    const int* rp = d_rowptr + g * (N_ + 1);
    const int* cg = d_col + (size_t)g * E_;

    int beg = rp[node], end = rp[node + 1];
    float4 acc = make_float4(0.f, 0.f, 0.f, 0.f);
    int e = beg;
    for (; e + 4 <= end; e += 4) {
        int s0 = cg[e], s1 = cg[e + 1], s2 = cg[e + 2], s3 = cg[e + 3];
        float w0 = dv[s0], w1 = dv[s1], w2 = dv[s2], w3 = dv[s3];
        uint2 r0 = *(const uint2*)(hg + (size_t)s0 * F_ + c0);
        uint2 r1 = *(const uint2*)(hg + (size_t)s1 * F_ + c0);
        uint2 r2 = *(const uint2*)(hg + (size_t)s2 * F_ + c0);
        uint2 r3 = *(const uint2*)(hg + (size_t)s3 * F_ + c0);
        float2 a0 = __half22float2(*(__half2*)&r0.x), b0 = __half22float2(*(__half2*)&r0.y);
        float2 a1 = __half22float2(*(__half2*)&r1.x), b1 = __half22float2(*(__half2*)&r1.y);
        float2 a2 = __half22float2(*(__half2*)&r2.x), b2 = __half22float2(*(__half2*)&r2.y);
        float2 a3 = __half22float2(*(__half2*)&r3.x), b3 = __half22float2(*(__half2*)&r3.y);
        acc.x += w0 * a0.x + w1 * a1.x + w2 * a2.x + w3 * a3.x;
        acc.y += w0 * a0.y + w1 * a1.y + w2 * a2.y + w3 * a3.y;
        acc.z += w0 * b0.x + w1 * b1.x + w2 * b2.x + w3 * b3.x;
        acc.w += w0 * b0.y + w1 * b1.y + w2 * b2.y + w3 * b3.y;
    }
    for (; e < end; e++) {
        int s = cg[e];
        float w = dv[s];
        uint2 r = *(const uint2*)(hg + (size_t)s * F_ + c0);
        float2 a = __half22float2(*(__half2*)&r.x), b = __half22float2(*(__half2*)&r.y);
        acc.x += w * a.x; acc.y += w * a.y; acc.z += w * b.x; acc.w += w * b.y;
    }
    float di = dv[node];
    float di2 = di * di;
    uint2 rs = *(const uint2*)(hg + (size_t)node * F_ + c0);
    float2 sa = __half22float2(*(__half2*)&rs.x), sb = __half22float2(*(__half2*)&rs.y);
    float4 b4 = *(const float4*)(bias + c0);
    float4 o;
    o.x = di * acc.x + di2 * sa.x + b4.x;
    o.y = di * acc.y + di2 * sa.y + b4.y;
    o.z = di * acc.z + di2 * sb.x + b4.z;
    o.w = di * acc.w + di2 * sb.y + b4.w;
    *(float4*)(out + (size_t)g * NF + (size_t)node * F_ + c0) = o;
}

// ---------------- dual-source GCN aggregation + fused obf ------------------
__global__ void dual_agg_k(const __half* __restrict__ srcA_base,
                           const __half* __restrict__ srcB_base, int srcB_stride,
                           float* __restrict__ outA_base, float* __restrict__ outB_base,
                           const float* __restrict__ bias,
                           const float* __restrict__ cmp_base,
                           int part_base, int oth_mode)
{
    __shared__ float sobf[8];
    int tid = threadIdx.x;
    int warp = (blockIdx.x * blockDim.x + tid) >> 5;
    int lane = tid & 31;
    int wid = tid >> 5;
    int g = blockIdx.y;
    int c0 = lane * 4;
    float obf = 0.f;

    if (warp < N_) {
        int node = warp;
        const __half* hA = srcA_base + (size_t)g * NF;
        const __half* hB = srcB_base + (size_t)g * srcB_stride;
        const float* dv = d_dinv + g * N_;
        const int* rp = d_rowptr + g * (N_ + 1);
        const int* cg = d_col + (size_t)g * E_;

        int beg = rp[node], end = rp[node + 1];
        float4 accA = make_float4(0.f, 0.f, 0.f, 0.f);
        float4 accB = make_float4(0.f, 0.f, 0.f, 0.f);
        int e = beg;
        for (; e + 2 <= end; e += 2) {
            int s0 = cg[e], s1 = cg[e + 1];
            float w0 = dv[s0], w1 = dv[s1];
            uint2 a0 = *(const uint2*)(hA + (size_t)s0 * F_ + c0);
            uint2 a1 = *(const uint2*)(hA + (size_t)s1 * F_ + c0);
            uint2 b0 = *(const uint2*)(hB + (size_t)s0 * F_ + c0);
            uint2 b1 = *(const uint2*)(hB + (size_t)s1 * F_ + c0);
            float2 ax0 = __half22float2(*(__half2*)&a0.x), az0 = __half22float2(*(__half2*)&a0.y);
            float2 ax1 = __half22float2(*(__half2*)&a1.x), az1 = __half22float2(*(__half2*)&a1.y);
            float2 bx0 = __half22float2(*(__half2*)&b0.x), bz0 = __half22float2(*(__half2*)&b0.y);
            float2 bx1 = __half22float2(*(__half2*)&b1.x), bz1 = __half22float2(*(__half2*)&b1.y);
            accA.x += w0 * ax0.x + w1 * ax1.x;  accA.y += w0 * ax0.y + w1 * ax1.y;
            accA.z += w0 * az0.x + w1 * az1.x;  accA.w += w0 * az0.y + w1 * az1.y;
            accB.x += w0 * bx0.x + w1 * bx1.x;  accB.y += w0 * bx0.y + w1 * bx1.y;
            accB.z += w0 * bz0.x + w1 * bz1.x;  accB.w += w0 * bz0.y + w1 * bz1.y;
        }
        for (; e < end; e++) {
            int s = cg[e];
            float w = dv[s];
            uint2 a = *(const uint2*)(hA + (size_t)s * F_ + c0);
            uint2 b = *(const uint2*)(hB + (size_t)s * F_ + c0);
            float2 ax = __half22float2(*(__half2*)&a.x), az = __half22float2(*(__half2*)&a.y);
            float2 bx = __half22float2(*(__half2*)&b.x), bz = __half22float2(*(__half2*)&b.y);
            accA.x += w * ax.x; accA.y += w * ax.y; accA.z += w * az.x; accA.w += w * az.y;
            accB.x += w * bx.x; accB.y += w * bx.y; accB.z += w * bz.x; accB.w += w * bz.y;
        }
        float di = dv[node];
        float di2 = di * di;
        uint2 ra = *(const uint2*)(hA + (size_t)node * F_ + c0);
        uint2 rb = *(const uint2*)(hB + (size_t)node * F_ + c0);
        float2 sax = __half22float2(*(__half2*)&ra.x), saz = __half22float2(*(__half2*)&ra.y);
        float2 sbx = __half22float2(*(__half2*)&rb.x), sbz = __half22float2(*(__half2*)&rb.y);
        float4 b4 = *(const float4*)(bias + c0);

        float4 A;
        A.x = di * accA.x + di2 * sax.x;
        A.y = di * accA.y + di2 * sax.y;
        A.z = di * accA.z + di2 * saz.x;
        A.w = di * accA.w + di2 * saz.y;
        float4 B;
        B.x = di * accB.x + di2 * sbx.x;
        B.y = di * accB.y + di2 * sbx.y;
        B.z = di * accB.z + di2 * sbz.x;
        B.w = di * accB.w + di2 * sbz.y;

        float4 oA = make_float4(A.x + b4.x, A.y + b4.y, A.z + b4.z, A.w + b4.w);
        float4 oB;
        if (oth_mode) {
            oB.x = 0.5f * (B.x - A.x) + b4.x;
            oB.y = 0.5f * (B.y - A.y) + b4.y;
            oB.z = 0.5f * (B.z - A.z) + b4.z;
            oB.w = 0.5f * (B.w - A.w) + b4.w;
        } else {
            oB = make_float4(B.x + b4.x, B.y + b4.y, B.z + b4.z, B.w + b4.w);
        }
        size_t off = (size_t)g * NF + (size_t)node * F_ + c0;
        *(float4*)(outA_base + off) = oA;
        *(float4*)(outB_base + off) = oB;

        float4 cm = *(const float4*)(cmp_base + off);
        float dx = cm.x - oA.x, dy = cm.y - oA.y, dz = cm.z - oA.z, dw = cm.w - oA.w;
        obf = dx * dx + dy * dy + dz * dz + dw * dw;
    }

#pragma unroll
    for (int off = 16; off; off >>= 1) obf += __shfl_xor_sync(0xFFFFFFFFu, obf, off);
    if (lane == 0) sobf[wid] = obf;
    __syncthreads();
    if (tid == 0) {
        float s = 0.f;
#pragma unroll
        for (int w = 0; w < 8; w++) s += sobf[w];
        atomicAdd(&d_parts[part_base + g], s);
    }
}

// ------------------------- sum3 ⊕ compute_u ---------------------------------
__global__ void sum3_u_k(const float* __restrict__ att) {
    if (blockIdx.x < U_BLOCKS) {
        int g = blockIdx.x;
        int dcol = threadIdx.x;
        __shared__ float sv[F_];
        if (dcol < F_) {
            float m = d_gv[g * F_ + dcol] * (1.f / (float)N_);
            sv[dcol] = 1.f / (1.f + expf(-m));
        }
        __syncthreads();
        if (dcol < F_) {
            const float* row = att + ((size_t)g * F_ + dcol) * F_;
            float s = 0.f;
#pragma unroll 4
            for (int e = 0; e < F_; e++) s += row[e] * sv[e];
            d_u[g * F_ + dcol] = s;
        }
    } else {
        size_t i = (size_t)(blockIdx.x - U_BLOCKS) * blockDim.x + threadIdx.x;
        size_t H = NF / 2;
        if (i >= H) return;
        const __half2* h = (const __half2*)d_htmp;
        float2 a = __half22float2(h[i]);
        float2 b = __half22float2(h[H + i]);
        float2 c = __half22float2(h[2 * H + i]);
        ((__half2*)d_hS1)[i] = __floats2half2_rn(a.x + b.x + c.x, a.y + b.y + c.y);
    }
}

// ---------- fuse_feat + used_feat + comp_re + efin obf + finalize ----------
__global__ void fuse_comp_k(float* __restrict__ out) {
    __shared__ __align__(16) float su[G_ * F_];
    __shared__ float sred[3][8];
    int tid = threadIdx.x;
    int lane = tid & 31;
    int wid = tid >> 5;
    for (int i = tid; i < G_ * F_; i += blockDim.x) su[i] = d_u[i];
    __syncthreads();

    int node = blockIdx.x * 8 + wid;
    float l01 = 0.f, l02 = 0.f, l12 = 0.f;

    if (node < N_) {
        float4 e[G_];
#pragma unroll
        for (int j = 0; j < G_; j++)
            e[j] = *(const float4*)(d_enc + (size_t)j * NF + (size_t)node * F_ + lane * 4);
        {
            float4 o;
            float mx = (e[0].x + e[1].x + e[2].x) * (1.f / 3.f);
            float my = (e[0].y + e[1].y + e[2].y) * (1.f / 3.f);
            float mz = (e[0].z + e[1].z + e[2].z) * (1.f / 3.f);
            float mw = (e[0].w + e[1].w + e[2].w) * (1.f / 3.f);
            o.x = (mx > 0.f) ? mx : expm1f(mx);
            o.y = (my > 0.f) ? my : expm1f(my);
            o.z = (mz > 0.f) ? mz : expm1f(mz);
            o.w = (mw > 0.f) ? mw : expm1f(mw);
            *(float4*)(out + NF + (size_t)node * F_ + lane * 4) = o;
        }
        float dots[G_][G_];
#pragma unroll
        for (int i = 0; i < G_; i++) {
            float4 uu = *(const float4*)&su[i * F_ + lane * 4];
#pragma unroll
            for (int j = 0; j < G_; j++) {
                float p = e[j].x * uu.x + e[j].y * uu.y + e[j].z * uu.z + e[j].w * uu.w;
#pragma unroll
                for (int off = 16; off; off >>= 1) p += __shfl_xor_sync(0xFFFFFFFFu, p, off);
                dots[i][j] = p;
            }
        }
        if (lane == 0) {
            float* cb = out + 2 * NF;
#pragma unroll
            for (int i = 0; i < G_; i++) {
                float s[G_], tot = 0.f;
#pragma unroll
                for (int j = 0; j < G_; j++) { s[j] = 1.f / (1.f + expf(-dots[i][j])); tot += s[j]; }
                float inv = 1.f / tot;
#pragma unroll
                for (int j = 0; j < G_; j++) cb[(size_t)node * 9 + i * 3 + j] = s[j] * inv;
            }
        }
        float4 f[G_];
#pragma unroll
        for (int j = 0; j < G_; j++)
            f[j] = *(const float4*)(d_efin + (size_t)j * NF + (size_t)node * F_ + lane * 4);
        {
            float4 o;
            float mx = (f[0].x + f[1].x + f[2].x) * (1.f / 3.f);
            float my = (f[0].y + f[1].y + f[2].y) * (1.f / 3.f);
            float mz = (f[0].z + f[1].z + f[2].z) * (1.f / 3.f);
            float mw = (f[0].w + f[1].w + f[2].w) * (1.f / 3.f);
            o.x = 1.f / (1.f + expf(-mx));
            o.y = 1.f / (1.f + expf(-my));
            o.z = 1.f / (1.f + expf(-mz));
            o.w = 1.f / (1.f + expf(-mw));
            *(float4*)(out + (size_t)node * F_ + lane * 4) = o;
        }
        {
            float dx, dy, dz, dw;
            dx = f[0].x - f[1].x; dy = f[0].y - f[1].y; dz = f[0].z - f[1].z; dw = f[0].w - f[1].w;
            l01 = dx * dx + dy * dy + dz * dz + dw * dw;
            dx = f[0].x - f[2].x; dy = f[0].y - f[2].y; dz = f[0].z - f[2].z; dw = f[0].w - f[2].w;
            l02 = dx * dx + dy * dy + dz * dz + dw * dw;
            dx = f[1].x - f[2].x; dy = f[1].y - f[2].y; dz = f[1].z - f[2].z; dw = f[1].w - f[2].w;
            l12 = dx * dx + dy * dy + dz * dz + dw * dw;
        }
    }

#pragma unroll
    for (int off = 16; off; off >>= 1) {
        l01 += __shfl_xor_sync(0xFFFFFFFFu, l01, off);
        l02 += __shfl_xor_sync(0xFFFFFFFFu, l02, off);
        l12 += __shfl_xor_sync(0xFFFFFFFFu, l12, off);
    }
    if (lane == 0) { sred[0][wid] = l01; sred[1][wid] = l02; sred[2][wid] = l12; }
    __syncthreads();

    __shared__ int slast;
    if (tid == 0) {
        float a = 0.f, b = 0.f, c = 0.f;
#pragma unroll
        for (int w = 0; w < 8; w++) { a += sred[0][w]; b += sred[1][w]; c += sred[2][w]; }
        atomicAdd(&d_parts[6], a);
        atomicAdd(&d_parts[7], b);
        atomicAdd(&d_parts[8], c);
        __threadfence();
        slast = (atomicAdd(&d_done, 1) == FUSE_BLOCKS - 1);
    }
    __syncthreads();
    if (slast && tid == 0) {
        float obf1 = 0.f;
#pragma unroll
        for (int g = 0; g < G_; g++)
            obf1 += 0.5f * (sqrtf(d_parts[g]) + sqrtf(d_parts[3 + g]));
        float obf0 = 2.f * (sqrtf(d_parts[6]) + sqrtf(d_parts[7]) + sqrtf(d_parts[8]));
        out[2 * NF + 9 * (size_t)N_]     = obf1;
        out[2 * NF + 9 * (size_t)N_ + 1] = obf0;
    }
}

// ------------------------- host launcher -----------------------------------
extern "C" void kernel_launch(void* const* d_in, const int* in_sizes, int n_in,
                              void* d_out, int out_size)
{
    const float* x       = (const float*)d_in[0];
    const float* fc1_w   = (const float*)d_in[1];
    const float* fc1_b   = (const float*)d_in[2];
    const float* w_conv1 = (const float*)d_in[3];
    const float* b_conv1 = (const float*)d_in[4];
    const float* w_conv2 = (const float*)d_in[5];
    const float* b_conv2 = (const float*)d_in[6];
    const float* w_dconv1 = (const float*)d_in[7];
    const float* b_dconv1 = (const float*)d_in[8];
    const float* w_dconv2 = (const float*)d_in[9];
    const float* b_dconv2 = (const float*)d_in[10];
    const float* fc2_w   = (const float*)d_in[11];
    const float* fc2_b   = (const float*)d_in[12];
    const float* att_w   = (const float*)d_in[13];
    const void*  edges   = (const void*)d_in[14];
    float* out = (float*)d_out;

    float *pre, *conv1, *enc, *own2, *oth2, *ow1, *efin;
    __half *htmp, *h6, *hS1;
    cudaGetSymbolAddress((void**)&pre,   d_pre);
    cudaGetSymbolAddress((void**)&conv1, d_conv1);
    cudaGetSymbolAddress((void**)&enc,   d_enc);
    cudaGetSymbolAddress((void**)&own2,  d_own2);
    cudaGetSymbolAddress((void**)&oth2,  d_oth2);
    cudaGetSymbolAddress((void**)&ow1,   d_ow1);
    cudaGetSymbolAddress((void**)&efin,  d_efin);
    cudaGetSymbolAddress((void**)&htmp,  d_htmp);
    cudaGetSymbolAddress((void**)&h6,    d_h6);
    cudaGetSymbolAddress((void**)&hS1,   d_hS1);

    const int TB = 256;
    dim3 gemm_grid(GEMM_BX, G_);
    dim3 gemm_grid6(GEMM_BX, 2 * G_);
    dim3 agg_grid((N_ + 7) / 8, G_);
    dim3 scan_grid(SB_, G_);

    // L1: detect dtype ⊕ zero
    detect_zero_k<<<1 + (G_ * N_ + TB - 1) / TB, TB>>>(edges);
    // L2: fc1 GEMM ⊕ count_deg
    gemm_count_k<<<GEMM_BLOCKS + CSRB, TB>>>(x, fc1_w, fc1_b, pre, F_ * F_, F_, 0, edges);
    // L3-L4: scan
    scan_p1_k<<<scan_grid, TB>>>();
    scan_p3_k<<<scan_grid, TB>>>();
    // L5: conv1 GEMM ⊕ fill_csr
    gemm_fill_k<<<GEMM_BLOCKS + CSRB, TB>>>(pre, w_conv1, nullptr, htmp, 0, 0, 1, edges);
    // L6: agg -> conv1
    aggh_k<<<agg_grid, TB>>>(htmp, conv1, b_conv1);
    // L7: conv2 GEMM
    gemm_tf32_k<<<gemm_grid, TB>>>(conv1, w_conv2, nullptr, htmp, nullptr, nullptr, 0, 0, 1);
    // L8: agg -> enc
    aggh_k<<<agg_grid, TB>>>(htmp, enc, b_conv2);
    // L9: t1 GEMM ⊕ gv_reduce
    gemm_gv_k<<<GEMM_BLOCKS + GV_BLOCKS, TB>>>(enc, w_dconv1, nullptr, htmp, 0, 0, 1);
    // L10: sum3 ⊕ compute_u
    sum3_u_k<<<U_BLOCKS + SUM3_BLOCKS, TB>>>(att_w);
    // L11: level-1 dual agg (own1|oth1) + obf(conv1-own1)
    dual_agg_k<<<agg_grid, TB>>>(htmp, hS1, 0, ow1, ow1 + G_ * NF, b_dconv1, conv1, 3, 1);
    // L12: level-2 GEMM (6 slices)
    gemm_tf32_k<<<gemm_grid6, TB>>>(ow1, w_dconv2, nullptr, h6, nullptr, nullptr, 0, 0, 1);
    // L13: level-2 dual agg (own2|oth2) + obf(pre-own2)
    dual_agg_k<<<agg_grid, TB>>>(h6, h6 + G_ * NF, NF, own2, oth2, b_dconv2, pre, 0, 0);
    // L14: fc2 GEMM (K=256 fused)
    gemm_tf32_k<<<gemm_grid, TB>>>(own2, fc2_w, fc2_b, efin, oth2, fc2_w + F_ * F_, 0, 0, 0);
    // L15: outputs (+fused finalize)
    fuse_comp_k<<<FUSE_BLOCKS, TB>>>(out);
}

// round 15
// speedup vs baseline: 1.1621x; 1.0338x over previous
#include <cuda_runtime.h>
#include <cuda_fp16.h>
#include <math.h>
#include <stdint.h>

#define N_ 50000
#define F_ 128
#define G_ 3
#define E_ 600000
#define NF ((size_t)N_ * F_)
#define SB_ 49
#define GEMM_BX 391
#define GEMM_BLOCKS (G_ * GEMM_BX)
#define CSRB 256
#define GV_BLOCKS (98 * G_)
#define U_BLOCKS G_
#define SUM3_BLOCKS ((int)((NF / 2 + 255) / 256))
#define FUSE_BLOCKS ((N_ + 7) / 8)

// fp16 GEMM smem layout (halves)
#define XSH 40
#define WSH 136
#define XS_HALVES (128 * XSH)
#define WS_HALVES (32 * WSH)

// ------------------------- static device scratch -------------------------
__device__ __align__(16) float d_pre  [G_ * N_ * F_];
__device__ __align__(16) float d_conv1[G_ * N_ * F_];
__device__ __align__(16) float d_enc  [G_ * N_ * F_];
__device__ __align__(16) float d_efin [G_ * N_ * F_];
__device__ __align__(16) __half d_htmp [G_ * N_ * F_];
__device__ __align__(16) __half d_ow1h [2 * G_ * N_ * F_];  // fp16 [own1|oth1]
__device__ __align__(16) __half d_h6   [2 * G_ * N_ * F_];
__device__ __align__(16) __half d_own2h[G_ * N_ * F_];
__device__ __align__(16) __half d_oth2h[G_ * N_ * F_];
__device__ __align__(16) __half d_hS1  [N_ * F_];

__device__ int   d_deg   [G_ * N_];
__device__ int   d_rowptr[G_ * (N_ + 1)];
__device__ int   d_cur   [G_ * N_];
__device__ int   d_col   [G_ * E_];
__device__ int   d_bsum  [G_ * SB_];
__device__ __align__(16) float d_dinv  [G_ * N_];
__device__ float d_gv    [G_ * F_];
__device__ __align__(16) float d_u     [G_ * F_];
__device__ float d_parts [16];
__device__ int   d_e64;
__device__ int   d_done;

// ------------------------- edge load helper -------------------------------
__device__ __forceinline__ int load_edge(const void* edges, size_t idx, int e64) {
    if (e64) return (int)((const long long*)edges)[idx];
    return ((const int*)edges)[idx];
}

// ------------------------- L1: detect dtype + zero -------------------------
__global__ void detect_zero_k(const void* __restrict__ edges) {
    if (blockIdx.x == 0) {
        const unsigned int* w = (const unsigned int*)edges;
        __shared__ int any;
        if (threadIdx.x == 0) any = 0;
        __syncthreads();
        for (int i = threadIdx.x; i < 2048; i += blockDim.x)
            if (w[2 * i + 1] != 0u) any = 1;
        __syncthreads();
        if (threadIdx.x == 0) { d_e64 = any ? 0 : 1; d_done = 0; }
    } else {
        int i = (blockIdx.x - 1) * blockDim.x + threadIdx.x;
        if (i < G_ * N_) d_deg[i] = 0;
        if (i < G_ * F_) d_gv[i] = 0.f;
        if (i < 16) d_parts[i] = 0.f;
    }
}

// ------------------------- grid-strided CSR bodies -------------------------
__device__ __forceinline__ void count_deg_body(const void* edges, int bx) {
    int e64 = d_e64;
    for (int i = bx * 256 + threadIdx.x; i < G_ * E_; i += CSRB * 256) {
        int g = i / E_, e = i - g * E_;
        int dst = load_edge(edges, (size_t)g * 2 * E_ + E_ + e, e64);
        atomicAdd(&d_deg[g * N_ + dst], 1);
    }
}

__device__ __forceinline__ void fill_csr_body(const void* edges, int bx) {
    int e64 = d_e64;
    for (int i = bx * 256 + threadIdx.x; i < G_ * E_; i += CSRB * 256) {
        int g = i / E_, e = i - g * E_;
        int src = load_edge(edges, (size_t)g * 2 * E_ + e, e64);
        int dst = load_edge(edges, (size_t)g * 2 * E_ + E_ + e, e64);
        int pos = atomicAdd(&d_cur[g * N_ + dst], 1);
        d_col[(size_t)g * E_ + pos] = src;
    }
}

// --- 2-phase multi-block prefix scan (+ dinv + cur fused) ---
__global__ void scan_p1_k() {
    int g = blockIdx.y, b = blockIdx.x;
    int tid = threadIdx.x;
    int base = b * 1024 + tid * 4;
    int v = 0;
#pragma unroll
    for (int j = 0; j < 4; j++) {
        int idx = base + j;
        if (idx < N_) v += d_deg[g * N_ + idx];
    }
    __shared__ int red[256];
    red[tid] = v;
    __syncthreads();
    for (int s = 128; s > 0; s >>= 1) {
        if (tid < s) red[tid] += red[tid + s];
        __syncthreads();
    }
    if (tid == 0) d_bsum[g * SB_ + b] = red[0];
}

__global__ void scan_p3_k() {
    int g = blockIdx.y, b = blockIdx.x;
    int tid = threadIdx.x;
    __shared__ int soff;
    if (tid == 0) {
        int acc = 0;
        for (int i = 0; i < b; i++) acc += d_bsum[g * SB_ + i];
        soff = acc;
    }
    int base = b * 1024 + tid * 4;
    int v[4]; int s = 0;
#pragma unroll
    for (int j = 0; j < 4; j++) {
        int idx = base + j;
        v[j] = (idx < N_) ? d_deg[g * N_ + idx] : 0;
        s += v[j];
    }
    __shared__ int sc[256];
    sc[tid] = s;
    __syncthreads();
    for (int st = 1; st < 256; st <<= 1) {
        int t = (tid >= st) ? sc[tid - st] : 0;
        __syncthreads();
        sc[tid] += t;
        __syncthreads();
    }
    int run = soff + sc[tid] - s;
    if (b == 0 && tid == 0) d_rowptr[g * (N_ + 1)] = 0;
#pragma unroll
    for (int j = 0; j < 4; j++) {
        int idx = base + j;
        if (idx < N_) {
            d_cur[g * N_ + idx] = run;
            run += v[j];
            d_rowptr[g * (N_ + 1) + idx + 1] = run;
            d_dinv[g * N_ + idx] = rsqrtf((float)(v[j] + 1));
        }
    }
}

// ------------------------- fp16 tensor-core GEMM ---------------------------
__device__ __forceinline__ uint32_t smem_u32(const void* p) {
    return (uint32_t)__cvta_generic_to_shared(p);
}

__device__ __forceinline__ void ldmat_x4(uint32_t* r, uint32_t addr) {
    asm volatile("ldmatrix.sync.aligned.m8n8.x4.shared.b16 {%0,%1,%2,%3}, [%4];"
        : "=r"(r[0]), "=r"(r[1]), "=r"(r[2]), "=r"(r[3]) : "r"(addr));
}

__device__ __forceinline__ void ldmat_x4t(uint32_t* r, uint32_t addr) {
    asm volatile("ldmatrix.sync.aligned.m8n8.x4.trans.shared.b16 {%0,%1,%2,%3}, [%4];"
        : "=r"(r[0]), "=r"(r[1]), "=r"(r[2]), "=r"(r[3]) : "r"(addr));
}

__device__ __forceinline__ void mma_f16(float* c, const uint32_t* a,
                                        uint32_t b0, uint32_t b1) {
    asm volatile(
        "mma.sync.aligned.m16n8k16.row.col.f32.f16.f16.f32 "
        "{%0,%1,%2,%3}, {%4,%5,%6,%7}, {%8,%9}, {%0,%1,%2,%3};"
        : "+f"(c[0]), "+f"(c[1]), "+f"(c[2]), "+f"(c[3])
        : "r"(a[0]), "r"(a[1]), "r"(a[2]), "r"(a[3]), "r"(b0), "r"(b1));
}

// HIN=0: fp32 X inputs; HIN=1: fp16 X inputs (direct smem copy, no cvt)
template<int HIN>
__device__ __forceinline__ void gemm_body(
    int g, int rb,
    const void* __restrict__ Xbase, const float* __restrict__ Wbase,
    const float* __restrict__ bbase, void* __restrict__ Ybase,
    const void* __restrict__ X2base, const float* __restrict__ W2base,
    int wstride, int bstride, int half_out)
{
    const float* Xf  = (const float*)Xbase + (size_t)g * NF;
    const float* X2f = X2base ? ((const float*)X2base + (size_t)g * NF) : nullptr;
    const __half* Xh  = (const __half*)Xbase + (size_t)g * NF;
    const __half* X2h = X2base ? ((const __half*)X2base + (size_t)g * NF) : nullptr;
    const float* W  = Wbase + (size_t)g * wstride;
    const float* bias = bbase ? (bbase + (size_t)g * bstride) : nullptr;
    int row0 = rb * 128;

    __shared__ __align__(16) __half sX[2][XS_HALVES];
    __shared__ __align__(16) __half sW[2][WS_HALVES];

    int tid = threadIdx.x;
    int lane = tid & 31;
    int wid = tid >> 5;
    int wm = (wid >> 1) * 32;
    int wn = (wid & 1) * 64;

    float acc[2][8][4];
#pragma unroll
    for (int mt = 0; mt < 2; mt++)
#pragma unroll
        for (int nt = 0; nt < 8; nt++)
#pragma unroll
            for (int q = 0; q < 4; q++) acc[mt][nt][q] = 0.f;

    int nchunks = X2base ? 8 : 4;

    int lrow = (lane & 7) + ((lane & 8) ? 8 : 0);
    int seg8 = (lane & 16) ? 8 : 0;
    uint32_t offA = (uint32_t)(((wm + lrow) * XSH + seg8) * 2);
    uint32_t offB = (uint32_t)((lrow * WSH + wn + seg8) * 2);
    uint32_t baseX[2] = { smem_u32(sX[0]), smem_u32(sX[1]) };
    uint32_t baseW[2] = { smem_u32(sW[0]), smem_u32(sW[1]) };

    float4 pxv[4];     // fp32 path
    uint2  pxh[4];     // fp16 path
    float4 pwv[4];
#define LOAD_CHUNK(ch)                                                        \
    {                                                                         \
        int k0 = ((ch) & 3) * 32;                                             \
        _Pragma("unroll")                                                     \
        for (int t = 0; t < 4; t++) {                                         \
            int idx = tid + t * 256;                                          \
            int r = idx >> 3, c = (idx & 7) * 4;                              \
            int row = row0 + r;                                               \
            if (HIN) {                                                        \
                const __half* Xc = ((ch) < 4) ? Xh : X2h;                     \
                pxh[t] = make_uint2(0u, 0u);                                  \
                if (row < N_) pxh[t] = *(const uint2*)(Xc + (size_t)row * 128 + k0 + c); \
            } else {                                                          \
                const float* Xc = ((ch) < 4) ? Xf : X2f;                      \
                pxv[t] = make_float4(0.f, 0.f, 0.f, 0.f);                     \
                if (row < N_) pxv[t] = *(const float4*)(Xc + (size_t)row * 128 + k0 + c); \
            }                                                                 \
            const float* Wc = ((ch) < 4) ? W : W2base;                        \
            int k = idx >> 5, c2 = (idx & 31) * 4;                            \
            pwv[t] = *(const float4*)(Wc + (size_t)(k0 + k) * 128 + c2);      \
        }                                                                     \
    }

#define STORE_CHUNK(bi)                                                       \
    {                                                                         \
        _Pragma("unroll")                                                     \
        for (int t = 0; t < 4; t++) {                                         \
            int idx = tid + t * 256;                                          \
            int r = idx >> 3, c = (idx & 7) * 4;                              \
            if (HIN) {                                                        \
                *(uint2*)&sX[bi][r * XSH + c] = pxh[t];                       \
            } else {                                                          \
                *(__half2*)&sX[bi][r * XSH + c]     = __floats2half2_rn(pxv[t].x, pxv[t].y); \
                *(__half2*)&sX[bi][r * XSH + c + 2] = __floats2half2_rn(pxv[t].z, pxv[t].w); \
            }                                                                 \
            int k = idx >> 5, c2 = (idx & 31) * 4;                            \
            *(__half2*)&sW[bi][k * WSH + c2]     = __floats2half2_rn(pwv[t].x, pwv[t].y); \
            *(__half2*)&sW[bi][k * WSH + c2 + 2] = __floats2half2_rn(pwv[t].z, pwv[t].w); \
        }                                                                     \
    }

    LOAD_CHUNK(0);
    STORE_CHUNK(0);
    __syncthreads();

    for (int chunk = 0; chunk < nchunks; chunk++) {
        int bi = chunk & 1;
        if (chunk + 1 < nchunks) LOAD_CHUNK(chunk + 1);

#pragma unroll
        for (int s = 0; s < 2; s++) {
            uint32_t a0[4], a1[4];
            ldmat_x4(a0, baseX[bi] + offA + (uint32_t)((s * 16) * 2));
            ldmat_x4(a1, baseX[bi] + offA + (uint32_t)((16 * XSH + s * 16) * 2));
#pragma unroll
            for (int ntp = 0; ntp < 4; ntp++) {
                uint32_t b[4];
                ldmat_x4t(b, baseW[bi] + offB + (uint32_t)((s * 16 * WSH + ntp * 16) * 2));
                mma_f16(acc[0][2 * ntp],     a0, b[0], b[1]);
                mma_f16(acc[1][2 * ntp],     a1, b[0], b[1]);
                mma_f16(acc[0][2 * ntp + 1], a0, b[2], b[3]);
                mma_f16(acc[1][2 * ntp + 1], a1, b[2], b[3]);
            }
        }

        if (chunk + 1 < nchunks) {
            STORE_CHUNK(bi ^ 1);
            __syncthreads();
        }
    }

    float* Yf = (float*)Ybase + (size_t)g * NF;
    __half* Yh = (__half*)Ybase + (size_t)g * NF;
#pragma unroll
    for (int mt = 0; mt < 2; mt++) {
        int r0 = row0 + wm + mt * 16 + (lane >> 2);
        int r1 = r0 + 8;
#pragma unroll
        for (int nt = 0; nt < 8; nt++) {
            int cb = wn + nt * 8 + 2 * (lane & 3);
            float bx = 0.f, by = 0.f;
            if (bias) { bx = bias[cb]; by = bias[cb + 1]; }
            float ox0 = acc[mt][nt][0] + bx, oy0 = acc[mt][nt][1] + by;
            float ox1 = acc[mt][nt][2] + bx, oy1 = acc[mt][nt][3] + by;
            if (half_out) {
                if (r0 < N_) *(__half2*)(Yh + (size_t)r0 * 128 + cb) = __floats2half2_rn(ox0, oy0);
                if (r1 < N_) *(__half2*)(Yh + (size_t)r1 * 128 + cb) = __floats2half2_rn(ox1, oy1);
            } else {
                if (r0 < N_) *(float2*)(Yf + (size_t)r0 * 128 + cb) = make_float2(ox0, oy0);
                if (r1 < N_) *(float2*)(Yf + (size_t)r1 * 128 + cb) = make_float2(ox1, oy1);
            }
        }
    }
#undef LOAD_CHUNK
#undef STORE_CHUNK
}

// plain GEMM, fp32 inputs
__global__ void __launch_bounds__(256) gemm_f32_k(
    const float* __restrict__ Xbase, const float* __restrict__ Wbase,
    const float* __restrict__ bbase, void* __restrict__ Ybase,
    const float* __restrict__ X2base, const float* __restrict__ W2base,
    int wstride, int bstride, int half_out)
{
    gemm_body<0>(blockIdx.y, blockIdx.x, Xbase, Wbase, bbase, Ybase,
                 X2base, W2base, wstride, bstride, half_out);
}

// plain GEMM, fp16 inputs
__global__ void __launch_bounds__(256) gemm_f16in_k(
    const __half* __restrict__ Xbase, const float* __restrict__ Wbase,
    const float* __restrict__ bbase, void* __restrict__ Ybase,
    const __half* __restrict__ X2base, const float* __restrict__ W2base,
    int wstride, int bstride, int half_out)
{
    gemm_body<1>(blockIdx.y, blockIdx.x, Xbase, Wbase, bbase, Ybase,
                 X2base, W2base, wstride, bstride, half_out);
}

// merged: GEMM ⊕ count_deg
__global__ void __launch_bounds__(256) gemm_count_k(
    const float* __restrict__ Xbase, const float* __restrict__ Wbase,
    const float* __restrict__ bbase, void* __restrict__ Ybase,
    int wstride, int bstride, int half_out, const void* __restrict__ edges)
{
    if (blockIdx.x < GEMM_BLOCKS) {
        int g = blockIdx.x / GEMM_BX;
        gemm_body<0>(g, blockIdx.x - g * GEMM_BX, Xbase, Wbase, bbase, Ybase,
                     nullptr, nullptr, wstride, bstride, half_out);
    } else {
        count_deg_body(edges, blockIdx.x - GEMM_BLOCKS);
    }
}

// merged: GEMM ⊕ fill_csr
__global__ void __launch_bounds__(256) gemm_fill_k(
    const float* __restrict__ Xbase, const float* __restrict__ Wbase,
    const float* __restrict__ bbase, void* __restrict__ Ybase,
    int wstride, int bstride, int half_out, const void* __restrict__ edges)
{
    if (blockIdx.x < GEMM_BLOCKS) {
        int g = blockIdx.x / GEMM_BX;
        gemm_body<0>(g, blockIdx.x - g * GEMM_BX, Xbase, Wbase, bbase, Ybase,
                     nullptr, nullptr, wstride, bstride, half_out);
    } else {
        fill_csr_body(edges, blockIdx.x - GEMM_BLOCKS);
    }
}

// merged: GEMM ⊕ gv_reduce
__global__ void __launch_bounds__(256) gemm_gv_k(
    const float* __restrict__ Xbase, const float* __restrict__ Wbase,
    const float* __restrict__ bbase, void* __restrict__ Ybase,
    int wstride, int bstride, int half_out)
{
    if (blockIdx.x < GEMM_BLOCKS) {
        int g = blockIdx.x / GEMM_BX;
        gemm_body<0>(g, blockIdx.x - g * GEMM_BX, Xbase, Wbase, bbase, Ybase,
                     nullptr, nullptr, wstride, bstride, half_out);
    } else {
        int j = blockIdx.x - GEMM_BLOCKS;
        int g = j / 98;
        int nb = j - g * 98;
        int f = threadIdx.x & 127;
        int half = threadIdx.x >> 7;
        int n0 = nb * 512 + half * 256;
        int nend = n0 + 256; if (nend > N_) nend = N_;
        float s = 0.f;
        const float* eg = d_enc + (size_t)g * NF;
        for (int n = n0; n < nend; n++) s += eg[(size_t)n * F_ + f];
        atomicAdd(&d_gv[g * F_ + f], s);
    }
}

// ---------------- single-source GCN aggregation ---------------------------
__global__ void aggh_k(const __half* __restrict__ hbase, float* __restrict__ out,
                       const float* __restrict__ bias)
{
    int warp = (blockIdx.x * blockDim.x + threadIdx.x) >> 5;
    int lane = threadIdx.x & 31;
    if (warp >= N_) return;
    int g = blockIdx.y;
    int node = warp;
    int c0 = lane * 4;

    const __half* hg = hbase + (size_t)g * NF;
    const float* dv = d_dinv + g * N_;
    const int* rp = d_rowptr + g * (N_ + 1);
    const int* cg = d_col + (size_t)g * E_;

    int beg = rp[node], end = rp[node + 1];
    float4 acc = make_float4(0.f, 0.f, 0.f, 0.f);
    int e = beg;
    for (; e + 4 <= end; e += 4) {
        int s0 = cg[e], s1 = cg[e + 1], s2 = cg[e + 2], s3 = cg[e + 3];
        float w0 = dv[s0], w1 = dv[s1], w2 = dv[s2], w3 = dv[s3];
        uint2 r0 = *(const uint2*)(hg + (size_t)s0 * F_ + c0);
        uint2 r1 = *(const uint2*)(hg + (size_t)s1 * F_ + c0);
        uint2 r2 = *(const uint2*)(hg + (size_t)s2 * F_ + c0);
        uint2 r3 = *(const uint2*)(hg + (size_t)s3 * F_ + c0);
        float2 a0 = __half22float2(*(__half2*)&r0.x), b0 = __half22float2(*(__half2*)&r0.y);
        float2 a1 = __half22float2(*(__half2*)&r1.x), b1 = __half22float2(*(__half2*)&r1.y);
        float2 a2 = __half22float2(*(__half2*)&r2.x), b2 = __half22float2(*(__half2*)&r2.y);
        float2 a3 = __half22float2(*(__half2*)&r3.x), b3 = __half22float2(*(__half2*)&r3.y);
        acc.x += w0 * a0.x + w1 * a1.x + w2 * a2.x + w3 * a3.x;
        acc.y += w0 * a0.y + w1 * a1.y + w2 * a2.y + w3 * a3.y;
        acc.z += w0 * b0.x + w1 * b1.x + w2 * b2.x + w3 * b3.x;
        acc.w += w0 * b0.y + w1 * b1.y + w2 * b2.y + w3 * b3.y;
    }
    for (; e < end; e++) {
        int s = cg[e];
        float w = dv[s];
        uint2 r = *(const uint2*)(hg + (size_t)s * F_ + c0);
        float2 a = __half22float2(*(__half2*)&r.x), b = __half22float2(*(__half2*)&r.y);
        acc.x += w * a.x; acc.y += w * a.y; acc.z += w * b.x; acc.w += w * b.y;
    }
    float di = dv[node];
    float di2 = di * di;
    uint2 rs = *(const uint2*)(hg + (size_t)node * F_ + c0);
    float2 sa = __half22float2(*(__half2*)&rs.x), sb = __half22float2(*(__half2*)&rs.y);
    float4 b4 = *(const float4*)(bias + c0);
    float4 o;
    o.x = di * acc.x + di2 * sa.x + b4.x;
    o.y = di * acc.y + di2 * sa.y + b4.y;
    o.z = di * acc.z + di2 * sb.x + b4.z;
    o.w = di * acc.w + di2 * sb.y + b4.w;
    *(float4*)(out + (size_t)g * NF + (size_t)node * F_ + c0) = o;
}

// ---------------- dual-source GCN aggregation + fused obf ------------------
__global__ void dual_agg_k(const __half* __restrict__ srcA_base,
                           const __half* __restrict__ srcB_base, int srcB_stride,
                           void* __restrict__ outA_base, void* __restrict__ outB_base,
                           const float* __restrict__ bias,
                           const float* __restrict__ cmp_base,
                           int part_base, int oth_mode, int out_half)
{
    __shared__ float sobf[8];
    int tid = threadIdx.x;
    int warp = (blockIdx.x * blockDim.x + tid) >> 5;
    int lane = tid & 31;
    int wid = tid >> 5;
    int g = blockIdx.y;
    int c0 = lane * 4;
    float obf = 0.f;

    if (warp < N_) {
        int node = warp;
        const __half* hA = srcA_base + (size_t)g * NF;
        const __half* hB = srcB_base + (size_t)g * srcB_stride;
        const float* dv = d_dinv + g * N_;
        const int* rp = d_rowptr + g * (N_ + 1);
        const int* cg = d_col + (size_t)g * E_;

        int beg = rp[node], end = rp[node + 1];
        float4 accA = make_float4(0.f, 0.f, 0.f, 0.f);
        float4 accB = make_float4(0.f, 0.f, 0.f, 0.f);
        int e = beg;
        for (; e + 2 <= end; e += 2) {
            int s0 = cg[e], s1 = cg[e + 1];
            float w0 = dv[s0], w1 = dv[s1];
            uint2 a0 = *(const uint2*)(hA + (size_t)s0 * F_ + c0);
            uint2 a1 = *(const uint2*)(hA + (size_t)s1 * F_ + c0);
            uint2 b0 = *(const uint2*)(hB + (size_t)s0 * F_ + c0);
            uint2 b1 = *(const uint2*)(hB + (size_t)s1 * F_ + c0);
            float2 ax0 = __half22float2(*(__half2*)&a0.x), az0 = __half22float2(*(__half2*)&a0.y);
            float2 ax1 = __half22float2(*(__half2*)&a1.x), az1 = __half22float2(*(__half2*)&a1.y);
            float2 bx0 = __half22float2(*(__half2*)&b0.x), bz0 = __half22float2(*(__half2*)&b0.y);
            float2 bx1 = __half22float2(*(__half2*)&b1.x), bz1 = __half22float2(*(__half2*)&b1.y);
            accA.x += w0 * ax0.x + w1 * ax1.x;  accA.y += w0 * ax0.y + w1 * ax1.y;
            accA.z += w0 * az0.x + w1 * az1.x;  accA.w += w0 * az0.y + w1 * az1.y;
            accB.x += w0 * bx0.x + w1 * bx1.x;  accB.y += w0 * bx0.y + w1 * bx1.y;
            accB.z += w0 * bz0.x + w1 * bz1.x;  accB.w += w0 * bz0.y + w1 * bz1.y;
        }
        for (; e < end; e++) {
            int s = cg[e];
            float w = dv[s];
            uint2 a = *(const uint2*)(hA + (size_t)s * F_ + c0);
            uint2 b = *(const uint2*)(hB + (size_t)s * F_ + c0);
            float2 ax = __half22float2(*(__half2*)&a.x), az = __half22float2(*(__half2*)&a.y);
            float2 bx = __half22float2(*(__half2*)&b.x), bz = __half22float2(*(__half2*)&b.y);
            accA.x += w * ax.x; accA.y += w * ax.y; accA.z += w * az.x; accA.w += w * az.y;
            accB.x += w * bx.x; accB.y += w * bx.y; accB.z += w * bz.x; accB.w += w * bz.y;
        }
        float di = dv[node];
        float di2 = di * di;
        uint2 ra = *(const uint2*)(hA + (size_t)node * F_ + c0);
        uint2 rb = *(const uint2*)(hB + (size_t)node * F_ + c0);
        float2 sax = __half22float2(*(__half2*)&ra.x), saz = __half22float2(*(__half2*)&ra.y);
        float2 sbx = __half22float2(*(__half2*)&rb.x), sbz = __half22float2(*(__half2*)&rb.y);
        float4 b4 = *(const float4*)(bias + c0);

        float4 A;
        A.x = di * accA.x + di2 * sax.x;
        A.y = di * accA.y + di2 * sax.y;
        A.z = di * accA.z + di2 * saz.x;
        A.w = di * accA.w + di2 * saz.y;
        float4 B;
        B.x = di * accB.x + di2 * sbx.x;
        B.y = di * accB.y + di2 * sbx.y;
        B.z = di * accB.z + di2 * sbz.x;
        B.w = di * accB.w + di2 * sbz.y;

        float4 oA = make_float4(A.x + b4.x, A.y + b4.y, A.z + b4.z, A.w + b4.w);
        float4 oB;
        if (oth_mode) {
            oB.x = 0.5f * (B.x - A.x) + b4.x;
            oB.y = 0.5f * (B.y - A.y) + b4.y;
            oB.z = 0.5f * (B.z - A.z) + b4.z;
            oB.w = 0.5f * (B.w - A.w) + b4.w;
        } else {
            oB = make_float4(B.x + b4.x, B.y + b4.y, B.z + b4.z, B.w + b4.w);
        }
        size_t off = (size_t)g * NF + (size_t)node * F_ + c0;
        if (out_half) {
            __half* oAp = (__half*)outA_base + off;
            __half* oBp = (__half*)outB_base + off;
            *(__half2*)oAp = __floats2half2_rn(oA.x, oA.y);
            *(__half2*)(oAp + 2) = __floats2half2_rn(oA.z, oA.w);
            *(__half2*)oBp = __floats2half2_rn(oB.x, oB.y);
            *(__half2*)(oBp + 2) = __floats2half2_rn(oB.z, oB.w);
        } else {
            *(float4*)((float*)outA_base + off) = oA;
            *(float4*)((float*)outB_base + off) = oB;
        }

        float4 cm = *(const float4*)(cmp_base + off);
        float dx = cm.x - oA.x, dy = cm.y - oA.y, dz = cm.z - oA.z, dw = cm.w - oA.w;
        obf = dx * dx + dy * dy + dz * dz + dw * dw;
    }

#pragma unroll
    for (int off = 16; off; off >>= 1) obf += __shfl_xor_sync(0xFFFFFFFFu, obf, off);
    if (lane == 0) sobf[wid] = obf;
    __syncthreads();
    if (tid == 0) {
        float s = 0.f;
#pragma unroll
        for (int w = 0; w < 8; w++) s += sobf[w];
        atomicAdd(&d_parts[part_base + g], s);
    }
}

// ------------------------- sum3 ⊕ compute_u ---------------------------------
__global__ void sum3_u_k(const float* __restrict__ att) {
    if (blockIdx.x < U_BLOCKS) {
        int g = blockIdx.x;
        int dcol = threadIdx.x;
        __shared__ float sv[F_];
        if (dcol < F_) {
            float m = d_gv[g * F_ + dcol] * (1.f / (float)N_);
            sv[dcol] = 1.f / (1.f + expf(-m));
        }
        __syncthreads();
        if (dcol < F_) {
            const float* row = att + ((size_t)g * F_ + dcol) * F_;
            float s = 0.f;
#pragma unroll 4
            for (int e = 0; e < F_; e++) s += row[e] * sv[e];
            d_u[g * F_ + dcol] = s;
        }
    } else {
        size_t i = (size_t)(blockIdx.x - U_BLOCKS) * blockDim.x + threadIdx.x;
        size_t H = NF / 2;
        if (i >= H) return;
        const __half2* h = (const __half2*)d_htmp;
        float2 a = __half22float2(h[i]);
        float2 b = __half22float2(h[H + i]);
        float2 c = __half22float2(h[2 * H + i]);
        ((__half2*)d_hS1)[i] = __floats2half2_rn(a.x + b.x + c.x, a.y + b.y + c.y);
    }
}

// ---------- fuse_feat + used_feat + comp_re + efin obf + finalize ----------
__global__ void fuse_comp_k(float* __restrict__ out) {
    __shared__ __align__(16) float su[G_ * F_];
    __shared__ float sred[3][8];
    int tid = threadIdx.x;
    int lane = tid & 31;
    int wid = tid >> 5;
    for (int i = tid; i < G_ * F_; i += blockDim.x) su[i] = d_u[i];
    __syncthreads();

    int node = blockIdx.x * 8 + wid;
    float l01 = 0.f, l02 = 0.f, l12 = 0.f;

    if (node < N_) {
        float4 e[G_];
#pragma unroll
        for (int j = 0; j < G_; j++)
            e[j] = *(const float4*)(d_enc + (size_t)j * NF + (size_t)node * F_ + lane * 4);
        {
            float4 o;
            float mx = (e[0].x + e[1].x + e[2].x) * (1.f / 3.f);
            float my = (e[0].y + e[1].y + e[2].y) * (1.f / 3.f);
            float mz = (e[0].z + e[1].z + e[2].z) * (1.f / 3.f);
            float mw = (e[0].w + e[1].w + e[2].w) * (1.f / 3.f);
            o.x = (mx > 0.f) ? mx : expm1f(mx);
            o.y = (my > 0.f) ? my : expm1f(my);
            o.z = (mz > 0.f) ? mz : expm1f(mz);
            o.w = (mw > 0.f) ? mw : expm1f(mw);
            *(float4*)(out + NF + (size_t)node * F_ + lane * 4) = o;
        }
        float dots[G_][G_];
#pragma unroll
        for (int i = 0; i < G_; i++) {
            float4 uu = *(const float4*)&su[i * F_ + lane * 4];
#pragma unroll
            for (int j = 0; j < G_; j++) {
                float p = e[j].x * uu.x + e[j].y * uu.y + e[j].z * uu.z + e[j].w * uu.w;
#pragma unroll
                for (int off = 16; off; off >>= 1) p += __shfl_xor_sync(0xFFFFFFFFu, p, off);
                dots[i][j] = p;
            }
        }
        if (lane == 0) {
            float* cb = out + 2 * NF;
#pragma unroll
            for (int i = 0; i < G_; i++) {
                float s[G_], tot = 0.f;
#pragma unroll
                for (int j = 0; j < G_; j++) { s[j] = 1.f / (1.f + expf(-dots[i][j])); tot += s[j]; }
                float inv = 1.f / tot;
#pragma unroll
                for (int j = 0; j < G_; j++) cb[(size_t)node * 9 + i * 3 + j] = s[j] * inv;
            }
        }
        float4 f[G_];
#pragma unroll
        for (int j = 0; j < G_; j++)
            f[j] = *(const float4*)(d_efin + (size_t)j * NF + (size_t)node * F_ + lane * 4);
        {
            float4 o;
            float mx = (f[0].x + f[1].x + f[2].x) * (1.f / 3.f);
            float my = (f[0].y + f[1].y + f[2].y) * (1.f / 3.f);
            float mz = (f[0].z + f[1].z + f[2].z) * (1.f / 3.f);
            float mw = (f[0].w + f[1].w + f[2].w) * (1.f / 3.f);
            o.x = 1.f / (1.f + expf(-mx));
            o.y = 1.f / (1.f + expf(-my));
            o.z = 1.f / (1.f + expf(-mz));
            o.w = 1.f / (1.f + expf(-mw));
            *(float4*)(out + (size_t)node * F_ + lane * 4) = o;
        }
        {
            float dx, dy, dz, dw;
            dx = f[0].x - f[1].x; dy = f[0].y - f[1].y; dz = f[0].z - f[1].z; dw = f[0].w - f[1].w;
            l01 = dx * dx + dy * dy + dz * dz + dw * dw;
            dx = f[0].x - f[2].x; dy = f[0].y - f[2].y; dz = f[0].z - f[2].z; dw = f[0].w - f[2].w;
            l02 = dx * dx + dy * dy + dz * dz + dw * dw;
            dx = f[1].x - f[2].x; dy = f[1].y - f[2].y; dz = f[1].z - f[2].z; dw = f[1].w - f[2].w;
            l12 = dx * dx + dy * dy + dz * dz + dw * dw;
        }
    }

#pragma unroll
    for (int off = 16; off; off >>= 1) {
        l01 += __shfl_xor_sync(0xFFFFFFFFu, l01, off);
        l02 += __shfl_xor_sync(0xFFFFFFFFu, l02, off);
        l12 += __shfl_xor_sync(0xFFFFFFFFu, l12, off);
    }
    if (lane == 0) { sred[0][wid] = l01; sred[1][wid] = l02; sred[2][wid] = l12; }
    __syncthreads();

    __shared__ int slast;
    if (tid == 0) {
        float a = 0.f, b = 0.f, c = 0.f;
#pragma unroll
        for (int w = 0; w < 8; w++) { a += sred[0][w]; b += sred[1][w]; c += sred[2][w]; }
        atomicAdd(&d_parts[6], a);
        atomicAdd(&d_parts[7], b);
        atomicAdd(&d_parts[8], c);
        __threadfence();
        slast = (atomicAdd(&d_done, 1) == FUSE_BLOCKS - 1);
    }
    __syncthreads();
    if (slast && tid == 0) {
        float obf1 = 0.f;
#pragma unroll
        for (int g = 0; g < G_; g++)
            obf1 += 0.5f * (sqrtf(d_parts[g]) + sqrtf(d_parts[3 + g]));
        float obf0 = 2.f * (sqrtf(d_parts[6]) + sqrtf(d_parts[7]) + sqrtf(d_parts[8]));
        out[2 * NF + 9 * (size_t)N_]     = obf1;
        out[2 * NF + 9 * (size_t)N_ + 1] = obf0;
    }
}

// ------------------------- host launcher -----------------------------------
extern "C" void kernel_launch(void* const* d_in, const int* in_sizes, int n_in,
                              void* d_out, int out_size)
{
    const float* x       = (const float*)d_in[0];
    const float* fc1_w   = (const float*)d_in[1];
    const float* fc1_b   = (const float*)d_in[2];
    const float* w_conv1 = (const float*)d_in[3];
    const float* b_conv1 = (const float*)d_in[4];
    const float* w_conv2 = (const float*)d_in[5];
    const float* b_conv2 = (const float*)d_in[6];
    const float* w_dconv1 = (const float*)d_in[7];
    const float* b_dconv1 = (const float*)d_in[8];
    const float* w_dconv2 = (const float*)d_in[9];
    const float* b_dconv2 = (const float*)d_in[10];
    const float* fc2_w   = (const float*)d_in[11];
    const float* fc2_b   = (const float*)d_in[12];
    const float* att_w   = (const float*)d_in[13];
    const void*  edges   = (const void*)d_in[14];
    float* out = (float*)d_out;

    float *pre, *conv1, *enc, *efin;
    __half *htmp, *h6, *hS1, *ow1h, *own2h, *oth2h;
    cudaGetSymbolAddress((void**)&pre,   d_pre);
    cudaGetSymbolAddress((void**)&conv1, d_conv1);
    cudaGetSymbolAddress((void**)&enc,   d_enc);
    cudaGetSymbolAddress((void**)&efin,  d_efin);
    cudaGetSymbolAddress((void**)&htmp,  d_htmp);
    cudaGetSymbolAddress((void**)&h6,    d_h6);
    cudaGetSymbolAddress((void**)&hS1,   d_hS1);
    cudaGetSymbolAddress((void**)&ow1h,  d_ow1h);
    cudaGetSymbolAddress((void**)&own2h, d_own2h);
    cudaGetSymbolAddress((void**)&oth2h, d_oth2h);

    const int TB = 256;
    dim3 gemm_grid(GEMM_BX, G_);
    dim3 gemm_grid6(GEMM_BX, 2 * G_);
    dim3 agg_grid((N_ + 7) / 8, G_);
    dim3 scan_grid(SB_, G_);

    // L1: detect dtype ⊕ zero
    detect_zero_k<<<1 + (G_ * N_ + TB - 1) / TB, TB>>>(edges);
    // L2: fc1 GEMM ⊕ count_deg
    gemm_count_k<<<GEMM_BLOCKS + CSRB, TB>>>(x, fc1_w, fc1_b, pre, F_ * F_, F_, 0, edges);
    // L3-L4: scan
    scan_p1_k<<<scan_grid, TB>>>();
    scan_p3_k<<<scan_grid, TB>>>();
    // L5: conv1 GEMM ⊕ fill_csr
    gemm_fill_k<<<GEMM_BLOCKS + CSRB, TB>>>(pre, w_conv1, nullptr, htmp, 0, 0, 1, edges);
    // L6: agg -> conv1
    aggh_k<<<agg_grid, TB>>>(htmp, conv1, b_conv1);
    // L7: conv2 GEMM
    gemm_f32_k<<<gemm_grid, TB>>>(conv1, w_conv2, nullptr, htmp, nullptr, nullptr, 0, 0, 1);
    // L8: agg -> enc
    aggh_k<<<agg_grid, TB>>>(htmp, enc, b_conv2);
    // L9: t1 GEMM ⊕ gv_reduce
    gemm_gv_k<<<GEMM_BLOCKS + GV_BLOCKS, TB>>>(enc, w_dconv1, nullptr, htmp, 0, 0, 1);
    // L10: sum3 ⊕ compute_u
    sum3_u_k<<<U_BLOCKS + SUM3_BLOCKS, TB>>>(att_w);
    // L11: level-1 dual agg (own1|oth1, fp16 out) + obf(conv1-own1)
    dual_agg_k<<<agg_grid, TB>>>(htmp, hS1, 0, ow1h, ow1h + G_ * NF, b_dconv1, conv1, 3, 1, 1);
    // L12: level-2 GEMM (6 slices, fp16 in)
    gemm_f16in_k<<<gemm_grid6, TB>>>(ow1h, w_dconv2, nullptr, h6, nullptr, nullptr, 0, 0, 1);
    // L13: level-2 dual agg (own2|oth2, fp16 out) + obf(pre-own2)
    dual_agg_k<<<agg_grid, TB>>>(h6, h6 + G_ * NF, NF, own2h, oth2h, b_dconv2, pre, 0, 0, 1);
    // L14: fc2 GEMM (K=256 fused, fp16 in)
    gemm_f16in_k<<<gemm_grid, TB>>>(own2h, fc2_w, fc2_b, efin, oth2h, fc2_w + F_ * F_, 0, 0, 0);
    // L15: outputs (+fused finalize)
    fuse_comp_k<<<FUSE_BLOCKS, TB>>>(out);
}

// round 16
// speedup vs baseline: 1.2251x; 1.0542x over previous
#include <cuda_runtime.h>
#include <cuda_fp16.h>
#include <math.h>
#include <stdint.h>

#define N_ 50000
#define F_ 128
#define G_ 3
#define E_ 600000
#define NF ((size_t)N_ * F_)
#define SB_ 49
#define GEMM_BX 391
#define GEMM_BLOCKS (G_ * GEMM_BX)
#define CSRB 256
#define GV_BLOCKS (98 * G_)
#define U_BLOCKS G_
#define SUM3_BLOCKS ((int)((NF / 2 + 255) / 256))
#define FUSE_BLOCKS ((N_ + 7) / 8)

// fp16 GEMM smem layout (halves)
#define XSH 40
#define WSH 136
#define XS_HALVES (128 * XSH)
#define WS_HALVES (32 * WSH)

// ------------------------- static device scratch -------------------------
__device__ __align__(16) float d_enc  [G_ * N_ * F_];
__device__ __align__(16) float d_efin [G_ * N_ * F_];
__device__ __align__(16) __half d_preh [G_ * N_ * F_];
__device__ __align__(16) __half d_cv1h [G_ * N_ * F_];
__device__ __align__(16) __half d_htmp [G_ * N_ * F_];
__device__ __align__(16) __half d_ow1h [2 * G_ * N_ * F_];
__device__ __align__(16) __half d_h6   [2 * G_ * N_ * F_];
__device__ __align__(16) __half d_own2h[G_ * N_ * F_];
__device__ __align__(16) __half d_oth2h[G_ * N_ * F_];
__device__ __align__(16) __half d_hS1  [N_ * F_];

__device__ int   d_deg   [G_ * N_];
__device__ int   d_rowptr[G_ * (N_ + 1)];
__device__ int   d_cur   [G_ * N_];
__device__ int   d_col   [G_ * E_];
__device__ int   d_bsum  [G_ * SB_];
__device__ __align__(16) float d_dinv  [G_ * N_];
__device__ float d_gv    [G_ * F_];
__device__ __align__(16) float d_u     [G_ * F_];
__device__ float d_parts [16];
__device__ int   d_e64;
__device__ int   d_done;

// ------------------------- edge load helper -------------------------------
__device__ __forceinline__ int load_edge(const void* edges, size_t idx, int e64) {
    if (e64) return (int)((const long long*)edges)[idx];
    return ((const int*)edges)[idx];
}

// ------------------------- L1: detect dtype + zero -------------------------
__global__ void detect_zero_k(const void* __restrict__ edges) {
    if (blockIdx.x == 0) {
        const unsigned int* w = (const unsigned int*)edges;
        __shared__ int any;
        if (threadIdx.x == 0) any = 0;
        __syncthreads();
        for (int i = threadIdx.x; i < 2048; i += blockDim.x)
            if (w[2 * i + 1] != 0u) any = 1;
        __syncthreads();
        if (threadIdx.x == 0) { d_e64 = any ? 0 : 1; d_done = 0; }
    } else {
        int i = (blockIdx.x - 1) * blockDim.x + threadIdx.x;
        if (i < G_ * N_) d_deg[i] = 0;
        if (i < G_ * F_) d_gv[i] = 0.f;
        if (i < 16) d_parts[i] = 0.f;
    }
}

// ------------------------- grid-strided CSR bodies -------------------------
__device__ __forceinline__ void count_deg_body(const void* edges, int bx) {
    int e64 = d_e64;
    for (int i = bx * 256 + threadIdx.x; i < G_ * E_; i += CSRB * 256) {
        int g = i / E_, e = i - g * E_;
        int dst = load_edge(edges, (size_t)g * 2 * E_ + E_ + e, e64);
        atomicAdd(&d_deg[g * N_ + dst], 1);
    }
}

__device__ __forceinline__ void fill_csr_body(const void* edges, int bx) {
    int e64 = d_e64;
    for (int i = bx * 256 + threadIdx.x; i < G_ * E_; i += CSRB * 256) {
        int g = i / E_, e = i - g * E_;
        int src = load_edge(edges, (size_t)g * 2 * E_ + e, e64);
        int dst = load_edge(edges, (size_t)g * 2 * E_ + E_ + e, e64);
        int pos = atomicAdd(&d_cur[g * N_ + dst], 1);
        d_col[(size_t)g * E_ + pos] = src;
    }
}

// --- 2-phase multi-block prefix scan (+ dinv + cur fused) ---
__global__ void scan_p1_k() {
    int g = blockIdx.y, b = blockIdx.x;
    int tid = threadIdx.x;
    int base = b * 1024 + tid * 4;
    int v = 0;
#pragma unroll
    for (int j = 0; j < 4; j++) {
        int idx = base + j;
        if (idx < N_) v += d_deg[g * N_ + idx];
    }
    __shared__ int red[256];
    red[tid] = v;
    __syncthreads();
    for (int s = 128; s > 0; s >>= 1) {
        if (tid < s) red[tid] += red[tid + s];
        __syncthreads();
    }
    if (tid == 0) d_bsum[g * SB_ + b] = red[0];
}

__global__ void scan_p3_k() {
    int g = blockIdx.y, b = blockIdx.x;
    int tid = threadIdx.x;
    __shared__ int soff;
    if (tid == 0) {
        int acc = 0;
        for (int i = 0; i < b; i++) acc += d_bsum[g * SB_ + i];
        soff = acc;
    }
    int base = b * 1024 + tid * 4;
    int v[4]; int s = 0;
#pragma unroll
    for (int j = 0; j < 4; j++) {
        int idx = base + j;
        v[j] = (idx < N_) ? d_deg[g * N_ + idx] : 0;
        s += v[j];
    }
    __shared__ int sc[256];
    sc[tid] = s;
    __syncthreads();
    for (int st = 1; st < 256; st <<= 1) {
        int t = (tid >= st) ? sc[tid - st] : 0;
        __syncthreads();
        sc[tid] += t;
        __syncthreads();
    }
    int run = soff + sc[tid] - s;
    if (b == 0 && tid == 0) d_rowptr[g * (N_ + 1)] = 0;
#pragma unroll
    for (int j = 0; j < 4; j++) {
        int idx = base + j;
        if (idx < N_) {
            d_cur[g * N_ + idx] = run;
            run += v[j];
            d_rowptr[g * (N_ + 1) + idx + 1] = run;
            d_dinv[g * N_ + idx] = rsqrtf((float)(v[j] + 1));
        }
    }
}

// ------------------------- fp16 tensor-core GEMM ---------------------------
__device__ __forceinline__ uint32_t smem_u32(const void* p) {
    return (uint32_t)__cvta_generic_to_shared(p);
}

__device__ __forceinline__ void ldmat_x4(uint32_t* r, uint32_t addr) {
    asm volatile("ldmatrix.sync.aligned.m8n8.x4.shared.b16 {%0,%1,%2,%3}, [%4];"
        : "=r"(r[0]), "=r"(r[1]), "=r"(r[2]), "=r"(r[3]) : "r"(addr));
}

__device__ __forceinline__ void ldmat_x4t(uint32_t* r, uint32_t addr) {
    asm volatile("ldmatrix.sync.aligned.m8n8.x4.trans.shared.b16 {%0,%1,%2,%3}, [%4];"
        : "=r"(r[0]), "=r"(r[1]), "=r"(r[2]), "=r"(r[3]) : "r"(addr));
}

__device__ __forceinline__ void mma_f16(float* c, const uint32_t* a,
                                        uint32_t b0, uint32_t b1) {
    asm volatile(
        "mma.sync.aligned.m16n8k16.row.col.f32.f16.f16.f32 "
        "{%0,%1,%2,%3}, {%4,%5,%6,%7}, {%8,%9}, {%0,%1,%2,%3};"
        : "+f"(c[0]), "+f"(c[1]), "+f"(c[2]), "+f"(c[3])
        : "r"(a[0]), "r"(a[1]), "r"(a[2]), "r"(a[3]), "r"(b0), "r"(b1));
}

// HIN=0: fp32 X inputs; HIN=1: fp16 X inputs (direct smem copy)
template<int HIN>
__device__ __forceinline__ void gemm_body(
    int g, int rb,
    const void* __restrict__ Xbase, const float* __restrict__ Wbase,
    const float* __restrict__ bbase, void* __restrict__ Ybase,
    const void* __restrict__ X2base, const float* __restrict__ W2base,
    int wstride, int bstride, int half_out)
{
    const float* Xf  = (const float*)Xbase + (size_t)g * NF;
    const float* X2f = X2base ? ((const float*)X2base + (size_t)g * NF) : nullptr;
    const __half* Xh  = (const __half*)Xbase + (size_t)g * NF;
    const __half* X2h = X2base ? ((const __half*)X2base + (size_t)g * NF) : nullptr;
    const float* W  = Wbase + (size_t)g * wstride;
    const float* bias = bbase ? (bbase + (size_t)g * bstride) : nullptr;
    int row0 = rb * 128;

    __shared__ __align__(16) __half sX[2][XS_HALVES];
    __shared__ __align__(16) __half sW[2][WS_HALVES];

    int tid = threadIdx.x;
    int lane = tid & 31;
    int wid = tid >> 5;
    int wm = (wid >> 1) * 32;
    int wn = (wid & 1) * 64;

    float acc[2][8][4];
#pragma unroll
    for (int mt = 0; mt < 2; mt++)
#pragma unroll
        for (int nt = 0; nt < 8; nt++)
#pragma unroll
            for (int q = 0; q < 4; q++) acc[mt][nt][q] = 0.f;

    int nchunks = X2base ? 8 : 4;

    int lrow = (lane & 7) + ((lane & 8) ? 8 : 0);
    int seg8 = (lane & 16) ? 8 : 0;
    uint32_t offA = (uint32_t)(((wm + lrow) * XSH + seg8) * 2);
    uint32_t offB = (uint32_t)((lrow * WSH + wn + seg8) * 2);
    uint32_t baseX[2] = { smem_u32(sX[0]), smem_u32(sX[1]) };
    uint32_t baseW[2] = { smem_u32(sW[0]), smem_u32(sW[1]) };

    float4 pxv[4];
    uint2  pxh[4];
    float4 pwv[4];
#define LOAD_CHUNK(ch)                                                        \
    {                                                                         \
        int k0 = ((ch) & 3) * 32;                                             \
        _Pragma("unroll")                                                     \
        for (int t = 0; t < 4; t++) {                                         \
            int idx = tid + t * 256;                                          \
            int r = idx >> 3, c = (idx & 7) * 4;                              \
            int row = row0 + r;                                               \
            if (HIN) {                                                        \
                const __half* Xc = ((ch) < 4) ? Xh : X2h;                     \
                pxh[t] = make_uint2(0u, 0u);                                  \
                if (row < N_) pxh[t] = *(const uint2*)(Xc + (size_t)row * 128 + k0 + c); \
            } else {                                                          \
                const float* Xc = ((ch) < 4) ? Xf : X2f;                      \
                pxv[t] = make_float4(0.f, 0.f, 0.f, 0.f);                     \
                if (row < N_) pxv[t] = *(const float4*)(Xc + (size_t)row * 128 + k0 + c); \
            }                                                                 \
            const float* Wc = ((ch) < 4) ? W : W2base;                        \
            int k = idx >> 5, c2 = (idx & 31) * 4;                            \
            pwv[t] = *(const float4*)(Wc + (size_t)(k0 + k) * 128 + c2);      \
        }                                                                     \
    }

#define STORE_CHUNK(bi)                                                       \
    {                                                                         \
        _Pragma("unroll")                                                     \
        for (int t = 0; t < 4; t++) {                                         \
            int idx = tid + t * 256;                                          \
            int r = idx >> 3, c = (idx & 7) * 4;                              \
            if (HIN) {                                                        \
                *(uint2*)&sX[bi][r * XSH + c] = pxh[t];                       \
            } else {                                                          \
                *(__half2*)&sX[bi][r * XSH + c]     = __floats2half2_rn(pxv[t].x, pxv[t].y); \
                *(__half2*)&sX[bi][r * XSH + c + 2] = __floats2half2_rn(pxv[t].z, pxv[t].w); \
            }                                                                 \
            int k = idx >> 5, c2 = (idx & 31) * 4;                            \
            *(__half2*)&sW[bi][k * WSH + c2]     = __floats2half2_rn(pwv[t].x, pwv[t].y); \
            *(__half2*)&sW[bi][k * WSH + c2 + 2] = __floats2half2_rn(pwv[t].z, pwv[t].w); \
        }                                                                     \
    }

    LOAD_CHUNK(0);
    STORE_CHUNK(0);
    __syncthreads();

    for (int chunk = 0; chunk < nchunks; chunk++) {
        int bi = chunk & 1;
        if (chunk + 1 < nchunks) LOAD_CHUNK(chunk + 1);

#pragma unroll
        for (int s = 0; s < 2; s++) {
            uint32_t a0[4], a1[4];
            ldmat_x4(a0, baseX[bi] + offA + (uint32_t)((s * 16) * 2));
            ldmat_x4(a1, baseX[bi] + offA + (uint32_t)((16 * XSH + s * 16) * 2));
#pragma unroll
            for (int ntp = 0; ntp < 4; ntp++) {
                uint32_t b[4];
                ldmat_x4t(b, baseW[bi] + offB + (uint32_t)((s * 16 * WSH + ntp * 16) * 2));
                mma_f16(acc[0][2 * ntp],     a0, b[0], b[1]);
                mma_f16(acc[1][2 * ntp],     a1, b[0], b[1]);
                mma_f16(acc[0][2 * ntp + 1], a0, b[2], b[3]);
                mma_f16(acc[1][2 * ntp + 1], a1, b[2], b[3]);
            }
        }

        if (chunk + 1 < nchunks) {
            STORE_CHUNK(bi ^ 1);
            __syncthreads();
        }
    }

    float* Yf = (float*)Ybase + (size_t)g * NF;
    __half* Yh = (__half*)Ybase + (size_t)g * NF;
#pragma unroll
    for (int mt = 0; mt < 2; mt++) {
        int r0 = row0 + wm + mt * 16 + (lane >> 2);
        int r1 = r0 + 8;
#pragma unroll
        for (int nt = 0; nt < 8; nt++) {
            int cb = wn + nt * 8 + 2 * (lane & 3);
            float bx = 0.f, by = 0.f;
            if (bias) { bx = bias[cb]; by = bias[cb + 1]; }
            float ox0 = acc[mt][nt][0] + bx, oy0 = acc[mt][nt][1] + by;
            float ox1 = acc[mt][nt][2] + bx, oy1 = acc[mt][nt][3] + by;
            if (half_out) {
                if (r0 < N_) *(__half2*)(Yh + (size_t)r0 * 128 + cb) = __floats2half2_rn(ox0, oy0);
                if (r1 < N_) *(__half2*)(Yh + (size_t)r1 * 128 + cb) = __floats2half2_rn(ox1, oy1);
            } else {
                if (r0 < N_) *(float2*)(Yf + (size_t)r0 * 128 + cb) = make_float2(ox0, oy0);
                if (r1 < N_) *(float2*)(Yf + (size_t)r1 * 128 + cb) = make_float2(ox1, oy1);
            }
        }
    }
#undef LOAD_CHUNK
#undef STORE_CHUNK
}

// plain GEMM, fp32 inputs
__global__ void __launch_bounds__(256) gemm_f32_k(
    const float* __restrict__ Xbase, const float* __restrict__ Wbase,
    const float* __restrict__ bbase, void* __restrict__ Ybase,
    const float* __restrict__ X2base, const float* __restrict__ W2base,
    int wstride, int bstride, int half_out)
{
    gemm_body<0>(blockIdx.y, blockIdx.x, Xbase, Wbase, bbase, Ybase,
                 X2base, W2base, wstride, bstride, half_out);
}

// plain GEMM, fp16 inputs
__global__ void __launch_bounds__(256) gemm_f16in_k(
    const __half* __restrict__ Xbase, const float* __restrict__ Wbase,
    const float* __restrict__ bbase, void* __restrict__ Ybase,
    const __half* __restrict__ X2base, const float* __restrict__ W2base,
    int wstride, int bstride, int half_out)
{
    gemm_body<1>(blockIdx.y, blockIdx.x, Xbase, Wbase, bbase, Ybase,
                 X2base, W2base, wstride, bstride, half_out);
}

// merged: GEMM(fp32 in) ⊕ count_deg — writes pre as fp16
__global__ void __launch_bounds__(256) gemm_count_k(
    const float* __restrict__ Xbase, const float* __restrict__ Wbase,
    const float* __restrict__ bbase, void* __restrict__ Ybase,
    int wstride, int bstride, int half_out, const void* __restrict__ edges)
{
    if (blockIdx.x < GEMM_BLOCKS) {
        int g = blockIdx.x / GEMM_BX;
        gemm_body<0>(g, blockIdx.x - g * GEMM_BX, Xbase, Wbase, bbase, Ybase,
                     nullptr, nullptr, wstride, bstride, half_out);
    } else {
        count_deg_body(edges, blockIdx.x - GEMM_BLOCKS);
    }
}

// merged: GEMM(fp16 in) ⊕ fill_csr — pre is fp16
__global__ void __launch_bounds__(256) gemm_fill_k(
    const __half* __restrict__ Xbase, const float* __restrict__ Wbase,
    const float* __restrict__ bbase, void* __restrict__ Ybase,
    int wstride, int bstride, int half_out, const void* __restrict__ edges)
{
    if (blockIdx.x < GEMM_BLOCKS) {
        int g = blockIdx.x / GEMM_BX;
        gemm_body<1>(g, blockIdx.x - g * GEMM_BX, Xbase, Wbase, bbase, Ybase,
                     nullptr, nullptr, wstride, bstride, half_out);
    } else {
        fill_csr_body(edges, blockIdx.x - GEMM_BLOCKS);
    }
}

// merged: GEMM(fp32 in) ⊕ gv_reduce — enc stays fp32
__global__ void __launch_bounds__(256) gemm_gv_k(
    const float* __restrict__ Xbase, const float* __restrict__ Wbase,
    const float* __restrict__ bbase, void* __restrict__ Ybase,
    int wstride, int bstride, int half_out)
{
    if (blockIdx.x < GEMM_BLOCKS) {
        int g = blockIdx.x / GEMM_BX;
        gemm_body<0>(g, blockIdx.x - g * GEMM_BX, Xbase, Wbase, bbase, Ybase,
                     nullptr, nullptr, wstride, bstride, half_out);
    } else {
        int j = blockIdx.x - GEMM_BLOCKS;
        int g = j / 98;
        int nb = j - g * 98;
        int f = threadIdx.x & 127;
        int half = threadIdx.x >> 7;
        int n0 = nb * 512 + half * 256;
        int nend = n0 + 256; if (nend > N_) nend = N_;
        float s = 0.f;
        const float* eg = d_enc + (size_t)g * NF;
        for (int n = n0; n < nend; n++) s += eg[(size_t)n * F_ + f];
        atomicAdd(&d_gv[g * F_ + f], s);
    }
}

// ---------------- single-source GCN aggregation (fp32 or fp16 out) --------
__global__ void aggh_k(const __half* __restrict__ hbase, void* __restrict__ out,
                       const float* __restrict__ bias, int out_half)
{
    int warp = (blockIdx.x * blockDim.x + threadIdx.x) >> 5;
    int lane = threadIdx.x & 31;
    if (warp >= N_) return;
    int g = blockIdx.y;
    int node = warp;
    int c0 = lane * 4;

    const __half* hg = hbase + (size_t)g * NF;
    const float* dv = d_dinv + g * N_;
    const int* rp = d_rowptr + g * (N_ + 1);
    const int* cg = d_col + (size_t)g * E_;

    int beg = rp[node], end = rp[node + 1];
    float4 acc = make_float4(0.f, 0.f, 0.f, 0.f);
    int e = beg;
    for (; e + 4 <= end; e += 4) {
        int s0 = cg[e], s1 = cg[e + 1], s2 = cg[e + 2], s3 = cg[e + 3];
        float w0 = dv[s0], w1 = dv[s1], w2 = dv[s2], w3 = dv[s3];
        uint2 r0 = *(const uint2*)(hg + (size_t)s0 * F_ + c0);
        uint2 r1 = *(const uint2*)(hg + (size_t)s1 * F_ + c0);
        uint2 r2 = *(const uint2*)(hg + (size_t)s2 * F_ + c0);
        uint2 r3 = *(const uint2*)(hg + (size_t)s3 * F_ + c0);
        float2 a0 = __half22float2(*(__half2*)&r0.x), b0 = __half22float2(*(__half2*)&r0.y);
        float2 a1 = __half22float2(*(__half2*)&r1.x), b1 = __half22float2(*(__half2*)&r1.y);
        float2 a2 = __half22float2(*(__half2*)&r2.x), b2 = __half22float2(*(__half2*)&r2.y);
        float2 a3 = __half22float2(*(__half2*)&r3.x), b3 = __half22float2(*(__half2*)&r3.y);
        acc.x += w0 * a0.x + w1 * a1.x + w2 * a2.x + w3 * a3.x;
        acc.y += w0 * a0.y + w1 * a1.y + w2 * a2.y + w3 * a3.y;
        acc.z += w0 * b0.x + w1 * b1.x + w2 * b2.x + w3 * b3.x;
        acc.w += w0 * b0.y + w1 * b1.y + w2 * b2.y + w3 * b3.y;
    }
    for (; e < end; e++) {
        int s = cg[e];
        float w = dv[s];
        uint2 r = *(const uint2*)(hg + (size_t)s * F_ + c0);
        float2 a = __half22float2(*(__half2*)&r.x), b = __half22float2(*(__half2*)&r.y);
        acc.x += w * a.x; acc.y += w * a.y; acc.z += w * b.x; acc.w += w * b.y;
    }
    float di = dv[node];
    float di2 = di * di;
    uint2 rs = *(const uint2*)(hg + (size_t)node * F_ + c0);
    float2 sa = __half22float2(*(__half2*)&rs.x), sb = __half22float2(*(__half2*)&rs.y);
    float4 b4 = *(const float4*)(bias + c0);
    float4 o;
    o.x = di * acc.x + di2 * sa.x + b4.x;
    o.y = di * acc.y + di2 * sa.y + b4.y;
    o.z = di * acc.z + di2 * sb.x + b4.z;
    o.w = di * acc.w + di2 * sb.y + b4.w;
    size_t off = (size_t)g * NF + (size_t)node * F_ + c0;
    if (out_half) {
        __half* op = (__half*)out + off;
        *(__half2*)op = __floats2half2_rn(o.x, o.y);
        *(__half2*)(op + 2) = __floats2half2_rn(o.z, o.w);
    } else {
        *(float4*)((float*)out + off) = o;
    }
}

// ---------------- dual-source GCN aggregation + fused obf ------------------
__global__ void dual_agg_k(const __half* __restrict__ srcA_base,
                           const __half* __restrict__ srcB_base, int srcB_stride,
                           void* __restrict__ outA_base, void* __restrict__ outB_base,
                           const float* __restrict__ bias,
                           const __half* __restrict__ cmp_base,
                           int part_base, int oth_mode, int out_half)
{
    __shared__ float sobf[8];
    int tid = threadIdx.x;
    int warp = (blockIdx.x * blockDim.x + tid) >> 5;
    int lane = tid & 31;
    int wid = tid >> 5;
    int g = blockIdx.y;
    int c0 = lane * 4;
    float obf = 0.f;

    if (warp < N_) {
        int node = warp;
        const __half* hA = srcA_base + (size_t)g * NF;
        const __half* hB = srcB_base + (size_t)g * srcB_stride;
        const float* dv = d_dinv + g * N_;
        const int* rp = d_rowptr + g * (N_ + 1);
        const int* cg = d_col + (size_t)g * E_;

        int beg = rp[node], end = rp[node + 1];
        float4 accA = make_float4(0.f, 0.f, 0.f, 0.f);
        float4 accB = make_float4(0.f, 0.f, 0.f, 0.f);
        int e = beg;
        for (; e + 2 <= end; e += 2) {
            int s0 = cg[e], s1 = cg[e + 1];
            float w0 = dv[s0], w1 = dv[s1];
            uint2 a0 = *(const uint2*)(hA + (size_t)s0 * F_ + c0);
            uint2 a1 = *(const uint2*)(hA + (size_t)s1 * F_ + c0);
            uint2 b0 = *(const uint2*)(hB + (size_t)s0 * F_ + c0);
            uint2 b1 = *(const uint2*)(hB + (size_t)s1 * F_ + c0);
            float2 ax0 = __half22float2(*(__half2*)&a0.x), az0 = __half22float2(*(__half2*)&a0.y);
            float2 ax1 = __half22float2(*(__half2*)&a1.x), az1 = __half22float2(*(__half2*)&a1.y);
            float2 bx0 = __half22float2(*(__half2*)&b0.x), bz0 = __half22float2(*(__half2*)&b0.y);
            float2 bx1 = __half22float2(*(__half2*)&b1.x), bz1 = __half22float2(*(__half2*)&b1.y);
            accA.x += w0 * ax0.x + w1 * ax1.x;  accA.y += w0 * ax0.y + w1 * ax1.y;
            accA.z += w0 * az0.x + w1 * az1.x;  accA.w += w0 * az0.y + w1 * az1.y;
            accB.x += w0 * bx0.x + w1 * bx1.x;  accB.y += w0 * bx0.y + w1 * bx1.y;
            accB.z += w0 * bz0.x + w1 * bz1.x;  accB.w += w0 * bz0.y + w1 * bz1.y;
        }
        for (; e < end; e++) {
            int s = cg[e];
            float w = dv[s];
            uint2 a = *(const uint2*)(hA + (size_t)s * F_ + c0);
            uint2 b = *(const uint2*)(hB + (size_t)s * F_ + c0);
            float2 ax = __half22float2(*(__half2*)&a.x), az = __half22float2(*(__half2*)&a.y);
            float2 bx = __half22float2(*(__half2*)&b.x), bz = __half22float2(*(__half2*)&b.y);
            accA.x += w * ax.x; accA.y += w * ax.y; accA.z += w * az.x; accA.w += w * az.y;
            accB.x += w * bx.x; accB.y += w * bx.y; accB.z += w * bz.x; accB.w += w * bz.y;
        }
        float di = dv[node];
        float di2 = di * di;
        uint2 ra = *(const uint2*)(hA + (size_t)node * F_ + c0);
        uint2 rb = *(const uint2*)(hB + (size_t)node * F_ + c0);
        float2 sax = __half22float2(*(__half2*)&ra.x), saz = __half22float2(*(__half2*)&ra.y);
        float2 sbx = __half22float2(*(__half2*)&rb.x), sbz = __half22float2(*(__half2*)&rb.y);
        float4 b4 = *(const float4*)(bias + c0);

        float4 A;
        A.x = di * accA.x + di2 * sax.x;
        A.y = di * accA.y + di2 * sax.y;
        A.z = di * accA.z + di2 * saz.x;
        A.w = di * accA.w + di2 * saz.y;
        float4 B;
        B.x = di * accB.x + di2 * sbx.x;
        B.y = di * accB.y + di2 * sbx.y;
        B.z = di * accB.z + di2 * sbz.x;
        B.w = di * accB.w + di2 * sbz.y;

        float4 oA = make_float4(A.x + b4.x, A.y + b4.y, A.z + b4.z, A.w + b4.w);
        float4 oB;
        if (oth_mode) {
            oB.x = 0.5f * (B.x - A.x) + b4.x;
            oB.y = 0.5f * (B.y - A.y) + b4.y;
            oB.z = 0.5f * (B.z - A.z) + b4.z;
            oB.w = 0.5f * (B.w - A.w) + b4.w;
        } else {
            oB = make_float4(B.x + b4.x, B.y + b4.y, B.z + b4.z, B.w + b4.w);
        }
        size_t off = (size_t)g * NF + (size_t)node * F_ + c0;
        if (out_half) {
            __half* oAp = (__half*)outA_base + off;
            __half* oBp = (__half*)outB_base + off;
            *(__half2*)oAp = __floats2half2_rn(oA.x, oA.y);
            *(__half2*)(oAp + 2) = __floats2half2_rn(oA.z, oA.w);
            *(__half2*)oBp = __floats2half2_rn(oB.x, oB.y);
            *(__half2*)(oBp + 2) = __floats2half2_rn(oB.z, oB.w);
        } else {
            *(float4*)((float*)outA_base + off) = oA;
            *(float4*)((float*)outB_base + off) = oB;
        }

        // obf term: (cmp - outA)^2, cmp is fp16
        uint2 cm2 = *(const uint2*)(cmp_base + off);
        float2 clo = __half22float2(*(__half2*)&cm2.x);
        float2 chi = __half22float2(*(__half2*)&cm2.y);
        float dx = clo.x - oA.x, dy = clo.y - oA.y, dz = chi.x - oA.z, dw = chi.y - oA.w;
        obf = dx * dx + dy * dy + dz * dz + dw * dw;
    }

#pragma unroll
    for (int off = 16; off; off >>= 1) obf += __shfl_xor_sync(0xFFFFFFFFu, obf, off);
    if (lane == 0) sobf[wid] = obf;
    __syncthreads();
    if (tid == 0) {
        float s = 0.f;
#pragma unroll
        for (int w = 0; w < 8; w++) s += sobf[w];
        atomicAdd(&d_parts[part_base + g], s);
    }
}

// ------------------------- sum3 ⊕ compute_u ---------------------------------
__global__ void sum3_u_k(const float* __restrict__ att) {
    if (blockIdx.x < U_BLOCKS) {
        int g = blockIdx.x;
        int dcol = threadIdx.x;
        __shared__ float sv[F_];
        if (dcol < F_) {
            float m = d_gv[g * F_ + dcol] * (1.f / (float)N_);
            sv[dcol] = 1.f / (1.f + expf(-m));
        }
        __syncthreads();
        if (dcol < F_) {
            const float* row = att + ((size_t)g * F_ + dcol) * F_;
            float s = 0.f;
#pragma unroll 4
            for (int e = 0; e < F_; e++) s += row[e] * sv[e];
            d_u[g * F_ + dcol] = s;
        }
    } else {
        size_t i = (size_t)(blockIdx.x - U_BLOCKS) * blockDim.x + threadIdx.x;
        size_t H = NF / 2;
        if (i >= H) return;
        const __half2* h = (const __half2*)d_htmp;
        float2 a = __half22float2(h[i]);
        float2 b = __half22float2(h[H + i]);
        float2 c = __half22float2(h[2 * H + i]);
        ((__half2*)d_hS1)[i] = __floats2half2_rn(a.x + b.x + c.x, a.y + b.y + c.y);
    }
}

// ---------- fuse_feat + used_feat + comp_re + efin obf + finalize ----------
__global__ void fuse_comp_k(float* __restrict__ out) {
    __shared__ __align__(16) float su[G_ * F_];
    __shared__ float sred[3][8];
    int tid = threadIdx.x;
    int lane = tid & 31;
    int wid = tid >> 5;
    for (int i = tid; i < G_ * F_; i += blockDim.x) su[i] = d_u[i];
    __syncthreads();

    int node = blockIdx.x * 8 + wid;
    float l01 = 0.f, l02 = 0.f, l12 = 0.f;

    if (node < N_) {
        float4 e[G_];
#pragma unroll
        for (int j = 0; j < G_; j++)
            e[j] = *(const float4*)(d_enc + (size_t)j * NF + (size_t)node * F_ + lane * 4);
        {
            float4 o;
            float mx = (e[0].x + e[1].x + e[2].x) * (1.f / 3.f);
            float my = (e[0].y + e[1].y + e[2].y) * (1.f / 3.f);
            float mz = (e[0].z + e[1].z + e[2].z) * (1.f / 3.f);
            float mw = (e[0].w + e[1].w + e[2].w) * (1.f / 3.f);
            o.x = (mx > 0.f) ? mx : expm1f(mx);
            o.y = (my > 0.f) ? my : expm1f(my);
            o.z = (mz > 0.f) ? mz : expm1f(mz);
            o.w = (mw > 0.f) ? mw : expm1f(mw);
            *(float4*)(out + NF + (size_t)node * F_ + lane * 4) = o;
        }
        float dots[G_][G_];
#pragma unroll
        for (int i = 0; i < G_; i++) {
            float4 uu = *(const float4*)&su[i * F_ + lane * 4];
#pragma unroll
            for (int j = 0; j < G_; j++) {
                float p = e[j].x * uu.x + e[j].y * uu.y + e[j].z * uu.z + e[j].w * uu.w;
#pragma unroll
                for (int off = 16; off; off >>= 1) p += __shfl_xor_sync(0xFFFFFFFFu, p, off);
                dots[i][j] = p;
            }
        }
        if (lane == 0) {
            float* cb = out + 2 * NF;
#pragma unroll
            for (int i = 0; i < G_; i++) {
                float s[G_], tot = 0.f;
#pragma unroll
                for (int j = 0; j < G_; j++) { s[j] = 1.f / (1.f + expf(-dots[i][j])); tot += s[j]; }
                float inv = 1.f / tot;
#pragma unroll
                for (int j = 0; j < G_; j++) cb[(size_t)node * 9 + i * 3 + j] = s[j] * inv;
            }
        }
        float4 f[G_];
#pragma unroll
        for (int j = 0; j < G_; j++)
            f[j] = *(const float4*)(d_efin + (size_t)j * NF + (size_t)node * F_ + lane * 4);
        {
            float4 o;
            float mx = (f[0].x + f[1].x + f[2].x) * (1.f / 3.f);
            float my = (f[0].y + f[1].y + f[2].y) * (1.f / 3.f);
            float mz = (f[0].z + f[1].z + f[2].z) * (1.f / 3.f);
            float mw = (f[0].w + f[1].w + f[2].w) * (1.f / 3.f);
            o.x = 1.f / (1.f + expf(-mx));
            o.y = 1.f / (1.f + expf(-my));
            o.z = 1.f / (1.f + expf(-mz));
            o.w = 1.f / (1.f + expf(-mw));
            *(float4*)(out + (size_t)node * F_ + lane * 4) = o;
        }
        {
            float dx, dy, dz, dw;
            dx = f[0].x - f[1].x; dy = f[0].y - f[1].y; dz = f[0].z - f[1].z; dw = f[0].w - f[1].w;
            l01 = dx * dx + dy * dy + dz * dz + dw * dw;
            dx = f[0].x - f[2].x; dy = f[0].y - f[2].y; dz = f[0].z - f[2].z; dw = f[0].w - f[2].w;
            l02 = dx * dx + dy * dy + dz * dz + dw * dw;
            dx = f[1].x - f[2].x; dy = f[1].y - f[2].y; dz = f[1].z - f[2].z; dw = f[1].w - f[2].w;
            l12 = dx * dx + dy * dy + dz * dz + dw * dw;
        }
    }

#pragma unroll
    for (int off = 16; off; off >>= 1) {
        l01 += __shfl_xor_sync(0xFFFFFFFFu, l01, off);
        l02 += __shfl_xor_sync(0xFFFFFFFFu, l02, off);
        l12 += __shfl_xor_sync(0xFFFFFFFFu, l12, off);
    }
    if (lane == 0) { sred[0][wid] = l01; sred[1][wid] = l02; sred[2][wid] = l12; }
    __syncthreads();

    __shared__ int slast;
    if (tid == 0) {
        float a = 0.f, b = 0.f, c = 0.f;
#pragma unroll
        for (int w = 0; w < 8; w++) { a += sred[0][w]; b += sred[1][w]; c += sred[2][w]; }
        atomicAdd(&d_parts[6], a);
        atomicAdd(&d_parts[7], b);
        atomicAdd(&d_parts[8], c);
        __threadfence();
        slast = (atomicAdd(&d_done, 1) == FUSE_BLOCKS - 1);
    }
    __syncthreads();
    if (slast && tid == 0) {
        float obf1 = 0.f;
#pragma unroll
        for (int g = 0; g < G_; g++)
            obf1 += 0.5f * (sqrtf(d_parts[g]) + sqrtf(d_parts[3 + g]));
        float obf0 = 2.f * (sqrtf(d_parts[6]) + sqrtf(d_parts[7]) + sqrtf(d_parts[8]));
        out[2 * NF + 9 * (size_t)N_]     = obf1;
        out[2 * NF + 9 * (size_t)N_ + 1] = obf0;
    }
}

// ------------------------- host launcher -----------------------------------
extern "C" void kernel_launch(void* const* d_in, const int* in_sizes, int n_in,
                              void* d_out, int out_size)
{
    const float* x       = (const float*)d_in[0];
    const float* fc1_w   = (const float*)d_in[1];
    const float* fc1_b   = (const float*)d_in[2];
    const float* w_conv1 = (const float*)d_in[3];
    const float* b_conv1 = (const float*)d_in[4];
    const float* w_conv2 = (const float*)d_in[5];
    const float* b_conv2 = (const float*)d_in[6];
    const float* w_dconv1 = (const float*)d_in[7];
    const float* b_dconv1 = (const float*)d_in[8];
    const float* w_dconv2 = (const float*)d_in[9];
    const float* b_dconv2 = (const float*)d_in[10];
    const float* fc2_w   = (const float*)d_in[11];
    const float* fc2_b   = (const float*)d_in[12];
    const float* att_w   = (const float*)d_in[13];
    const void*  edges   = (const void*)d_in[14];
    float* out = (float*)d_out;

    float *enc, *efin;
    __half *preh, *cv1h, *htmp, *h6, *hS1, *ow1h, *own2h, *oth2h;
    cudaGetSymbolAddress((void**)&enc,   d_enc);
    cudaGetSymbolAddress((void**)&efin,  d_efin);
    cudaGetSymbolAddress((void**)&preh,  d_preh);
    cudaGetSymbolAddress((void**)&cv1h,  d_cv1h);
    cudaGetSymbolAddress((void**)&htmp,  d_htmp);
    cudaGetSymbolAddress((void**)&h6,    d_h6);
    cudaGetSymbolAddress((void**)&hS1,   d_hS1);
    cudaGetSymbolAddress((void**)&ow1h,  d_ow1h);
    cudaGetSymbolAddress((void**)&own2h, d_own2h);
    cudaGetSymbolAddress((void**)&oth2h, d_oth2h);

    const int TB = 256;
    dim3 gemm_grid(GEMM_BX, G_);
    dim3 gemm_grid6(GEMM_BX, 2 * G_);
    dim3 agg_grid((N_ + 7) / 8, G_);
    dim3 scan_grid(SB_, G_);

    // L1: detect dtype ⊕ zero
    detect_zero_k<<<1 + (G_ * N_ + TB - 1) / TB, TB>>>(edges);
    // L2: fc1 GEMM (pre -> fp16) ⊕ count_deg
    gemm_count_k<<<GEMM_BLOCKS + CSRB, TB>>>(x, fc1_w, fc1_b, preh, F_ * F_, F_, 1, edges);
    // L3-L4: scan
    scan_p1_k<<<scan_grid, TB>>>();
    scan_p3_k<<<scan_grid, TB>>>();
    // L5: conv1 GEMM (fp16 in) ⊕ fill_csr
    gemm_fill_k<<<GEMM_BLOCKS + CSRB, TB>>>(preh, w_conv1, nullptr, htmp, 0, 0, 1, edges);
    // L6: agg -> conv1 (fp16 out)
    aggh_k<<<agg_grid, TB>>>(htmp, cv1h, b_conv1, 1);
    // L7: conv2 GEMM (fp16 in)
    gemm_f16in_k<<<gemm_grid, TB>>>(cv1h, w_conv2, nullptr, htmp, nullptr, nullptr, 0, 0, 1);
    // L8: agg -> enc (fp32 out, protects output precision)
    aggh_k<<<agg_grid, TB>>>(htmp, enc, b_conv2, 0);
    // L9: t1 GEMM ⊕ gv_reduce
    gemm_gv_k<<<GEMM_BLOCKS + GV_BLOCKS, TB>>>(enc, w_dconv1, nullptr, htmp, 0, 0, 1);
    // L10: sum3 ⊕ compute_u
    sum3_u_k<<<U_BLOCKS + SUM3_BLOCKS, TB>>>(att_w);
    // L11: level-1 dual agg (fp16 out) + obf(conv1-own1)
    dual_agg_k<<<agg_grid, TB>>>(htmp, hS1, 0, ow1h, ow1h + G_ * NF, b_dconv1, cv1h, 3, 1, 1);
    // L12: level-2 GEMM (6 slices, fp16 in)
    gemm_f16in_k<<<gemm_grid6, TB>>>(ow1h, w_dconv2, nullptr, h6, nullptr, nullptr, 0, 0, 1);
    // L13: level-2 dual agg (fp16 out) + obf(pre-own2)
    dual_agg_k<<<agg_grid, TB>>>(h6, h6 + G_ * NF, NF, own2h, oth2h, b_dconv2, preh, 0, 0, 1);
    // L14: fc2 GEMM (K=256 fused, fp16 in)
    gemm_f16in_k<<<gemm_grid, TB>>>(own2h, fc2_w, fc2_b, efin, oth2h, fc2_w + F_ * F_, 0, 0, 0);
    // L15: outputs (+fused finalize)
    fuse_comp_k<<<FUSE_BLOCKS, TB>>>(out);
}